// round 9
// baseline (speedup 1.0000x reference)
#include <cuda_runtime.h>
#include <math.h>
#include <stdint.h>

#define BB 64
#define SS 512
#define BS (BB*SS)
#define LL 16
#define WD 200
#define CD 30
#define FN 4
#define CF 120
#define KW 3
#define DD 320
#define HH 256
#define G4 1024
#define TT 17
#define LC 14

// ---------------- static scratch (no allocs allowed) ----------------
__device__ float d_z[BS * DD];                    // [B*S, 320]
__device__ float d_gx[2][(size_t)SS * BB * G4];   // [dir][S,B,1024]
__device__ float d_hs[2][(size_t)SS * BB * HH];   // [dir][S,B,256]
__device__ float d_h2[16][2][HH * 8];             // [grp][parity][k*8+b] h exchange
__device__ float d_emis[(size_t)BS * TT];         // [B,S,17]
__device__ float d_nd[BB];
__device__ int   d_ctr[16];

__device__ __forceinline__ float sigf(float x) { return 1.0f / (1.0f + expf(-x)); }

__device__ __forceinline__ int acq_load(const int* p) {
    int v;
    asm volatile("ld.global.acquire.gpu.b32 %0,[%1];" : "=r"(v) : "l"(p) : "memory");
    return v;
}

// ---- packed f32x2 helpers (sm_103a FFMA2) ----
__device__ __forceinline__ unsigned long long fdup(float w) {
    unsigned long long d;
    asm("mov.b64 %0, {%1, %1};" : "=l"(d) : "f"(w));
    return d;
}
__device__ __forceinline__ void ffma2(unsigned long long& a, unsigned long long x,
                                      unsigned long long y) {
    asm("fma.rn.f32x2 %0, %1, %2, %0;" : "+l"(a) : "l"(x), "l"(y));
}
__device__ __forceinline__ unsigned long long addx2(unsigned long long a,
                                                    unsigned long long b) {
    unsigned long long r;
    asm("add.rn.f32x2 %0, %1, %2;" : "=l"(r) : "l"(a), "l"(b));
    return r;
}
__device__ __forceinline__ float2 unpk(unsigned long long a) {
    float2 f;
    asm("mov.b64 {%0, %1}, %2;" : "=f"(f.x), "=f"(f.y) : "l"(a));
    return f;
}

// ---------------- init (reset barrier counters each launch) ----------------
__global__ void k_init() {
    int t = threadIdx.x;
    if (t < 16) d_ctr[t] = 0;
}

// ---------------- embeddings + char CNN + concat ----------------
__global__ void __launch_bounds__(128) k_embed(const int* __restrict__ tok,
                                               const int* __restrict__ ctok,
                                               const float* __restrict__ wemb,
                                               const float* __restrict__ cemb,
                                               const float* __restrict__ convw,
                                               const float* __restrict__ convb) {
    int w = blockIdx.x;  // word = b*S + s
    __shared__ float ce[LL][CD];
    __shared__ int cid[LL];
    int tid = threadIdx.x;
    if (tid < LL) cid[tid] = ctok[(size_t)w * LL + tid];
    __syncthreads();
    for (int i = tid; i < LL * CD; i += 128) {
        int l = i / CD, c = i % CD;
        ce[l][c] = cemb[cid[l] * CD + c];
    }
    __syncthreads();
    if (tid < CF) {
        int o = tid, ic = o >> 2;
        float w0 = convw[o * 3 + 0], w1 = convw[o * 3 + 1], w2 = convw[o * 3 + 2];
        float m = -1e30f;
#pragma unroll
        for (int t = 0; t < LC; t++) {
            float v = ce[t][ic] * w0 + ce[t + 1][ic] * w1 + ce[t + 2][ic] * w2;
            m = fmaxf(m, v);
        }
        d_z[(size_t)w * DD + WD + o] = m + convb[o];
    }
    const float* wr = wemb + (size_t)tok[w] * WD;
    for (int j = tid; j < WD; j += 128) d_z[(size_t)w * DD + j] = wr[j];
}

// ---------------- input-side GEMM with FFMA2: z[BS,320] @ W^T -> gx ----------------
__global__ void __launch_bounds__(256, 2) k_gemm_gx(const float* __restrict__ Wf,
                                                    const float* __restrict__ biasf,
                                                    const float* __restrict__ Wb,
                                                    const float* __restrict__ biasb) {
    int dir = blockIdx.z;
    const float* __restrict__ Wm = dir ? Wb : Wf;
    const float* __restrict__ bias = dir ? biasb : biasf;
    float* out = d_gx[dir];
    const float* __restrict__ Z = d_z;

    int mBase = blockIdx.x * 128;
    int nBase = blockIdx.y * 64;

    __shared__ float As[16][132];
    __shared__ float Bs[16][68];

    int tid = threadIdx.x;
    int ty = tid >> 4;
    int tx = tid & 15;

    unsigned long long acc2[8][2];
#pragma unroll
    for (int i = 0; i < 8; i++) { acc2[i][0] = 0ull; acc2[i][1] = 0ull; }

    for (int k0 = 0; k0 < DD; k0 += 16) {
#pragma unroll
        for (int r = 0; r < 2; r++) {
            int idx = tid + r * 256;
            int row = idx >> 2, kq = idx & 3;
            float4 v = *(const float4*)&Z[(size_t)(mBase + row) * DD + k0 + kq * 4];
            As[kq * 4 + 0][row] = v.x;
            As[kq * 4 + 1][row] = v.y;
            As[kq * 4 + 2][row] = v.z;
            As[kq * 4 + 3][row] = v.w;
        }
        {
            int row = tid >> 2, kq = tid & 3;
            float4 v = *(const float4*)&Wm[(size_t)(nBase + row) * DD + k0 + kq * 4];
            Bs[kq * 4 + 0][row] = v.x;
            Bs[kq * 4 + 1][row] = v.y;
            Bs[kq * 4 + 2][row] = v.z;
            Bs[kq * 4 + 3][row] = v.w;
        }
        __syncthreads();
#pragma unroll
        for (int kk = 0; kk < 16; kk++) {
            float4 a0 = *(const float4*)&As[kk][ty * 8];
            float4 a1 = *(const float4*)&As[kk][ty * 8 + 4];
            ulonglong2 bq = *(const ulonglong2*)&Bs[kk][tx * 4];
            float av[8] = {a0.x, a0.y, a0.z, a0.w, a1.x, a1.y, a1.z, a1.w};
#pragma unroll
            for (int i = 0; i < 8; i++) {
                unsigned long long ad = fdup(av[i]);
                ffma2(acc2[i][0], bq.x, ad);
                ffma2(acc2[i][1], bq.y, ad);
            }
        }
        __syncthreads();
    }

    float bq0 = bias[nBase + tx * 4 + 0], bq1 = bias[nBase + tx * 4 + 1];
    float bq2 = bias[nBase + tx * 4 + 2], bq3 = bias[nBase + tx * 4 + 3];
#pragma unroll
    for (int i = 0; i < 8; i++) {
        int m = mBase + ty * 8 + i;
        int b = m >> 9, s = m & 511;
        size_t ro = ((size_t)s * BB + b) * (size_t)G4 + nBase + tx * 4;
        float2 p0 = unpk(acc2[i][0]);
        float2 p1 = unpk(acc2[i][1]);
        float4 o4;
        o4.x = p0.x + bq0;
        o4.y = p0.y + bq1;
        o4.z = p1.x + bq2;
        o4.w = p1.y + bq3;
        *(float4*)&out[ro] = o4;
    }
}

// ---------------- BiLSTM: dual-chain CTAs, L2-barrier sync, W in regs --------------
// 64 CTAs x 512 thr. CTA = (dir, bg-pair, 32-k slice); advances TWO batch-group
// chains (A = 2*bp, B = 2*bp+1, same dir so same W slice) per iteration. While
// chain B computes, chain A's peer stores/counter become visible -> A's next spin
// hits immediately (sync latency hidden behind the other chain's compute).
// Per-chain mechanics identical to the proven R6 kernel (stcg/ldcg + atomic ctr).
__global__ void __launch_bounds__(512, 1)
k_lstm(const float* __restrict__ whf, const float* __restrict__ whb) {
    __shared__ float hA_sm[HH * 8];      // staged h(s-1) [k*8+b], chain A
    __shared__ float hB_sm[HH * 8];
    __shared__ float gA_sm[128 * 8];     // gates [local row][8 batch]
    __shared__ float gB_sm[128 * 8];
    __shared__ float cA_sm[32 * 8];      // cell state [k*8+b]
    __shared__ float cB_sm[32 * 8];

    int blk = blockIdx.x;
    int slice = blk & 7;
    int bp = (blk >> 3) & 3;
    int dir = blk >> 5;
    const float* Wd = dir ? whb : whf;
    int tid = threadIdx.x;
    int row = tid >> 2;          // 0..127 local gate row
    int sub = tid & 3;           // k-interleave lane
    int gt = row >> 5;           // gate 0..3
    int kl = row & 31;
    int ks = slice * 32;
    int gr = gt * 256 + ks + kl; // gate row in [0,1024)
    const float* gxp = d_gx[dir];
    float* hsp = d_hs[dir];
    int grpA = dir * 8 + 2 * bp;
    int grpB = grpA + 1;
    int b0A = (2 * bp) * 8;
    int b0B = b0A + 8;

    // W into registers: w_reg[kk] = W[gr][4*kk + sub]
    float w_reg[64];
    {
        const float* wr = Wd + (size_t)gr * HH + sub;
#pragma unroll
        for (int kk = 0; kk < 64; kk++) w_reg[kk] = __ldg(wr + 4 * kk);
    }
    if (tid < 256) { cA_sm[tid] = 0.f; cB_sm[tid] = 0.f; }
    __syncthreads();

    // preload gx for step 0 (sub==0 threads hold gxn for their row)
    float gxnA[8], gxnB[8];
    if (sub == 0) {
        int t0 = dir ? (SS - 1) : 0;
        const float* gxrA = gxp + ((size_t)t0 * BB + b0A) * G4 + gr;
        const float* gxrB = gxp + ((size_t)t0 * BB + b0B) * G4 + gr;
#pragma unroll
        for (int b = 0; b < 8; b++) {
            gxnA[b] = __ldg(gxrA + (size_t)b * G4);
            gxnB[b] = __ldg(gxrB + (size_t)b * G4);
        }
    }

    for (int s = 0; s < SS; s++) {
        int t = dir ? (SS - 1 - s) : s;
        int par = s & 1;

        // ================= chain A =================
        {
            unsigned long long a0 = 0ull, a1 = 0ull, a2 = 0ull, a3 = 0ull;
            if (s > 0) {
                if (tid == 0) {
                    int tgt = 8 * s;
                    while (acq_load(&d_ctr[grpA]) < tgt) {}
                }
                __syncthreads();
                {
                    int parp = par ^ 1;
                    float4 v = __ldcg((const float4*)(d_h2[grpA][parp]) + tid);
                    *(float4*)&hA_sm[tid * 4] = v;
                }
                __syncthreads();
                const float* hb = hA_sm + sub * 8;
#pragma unroll
                for (int kk = 0; kk < 64; kk++) {
                    unsigned long long wd = fdup(w_reg[kk]);
                    const ulonglong2* hp = (const ulonglong2*)(hb + kk * 32);
                    ulonglong2 q0 = hp[0];
                    ulonglong2 q1 = hp[1];
                    ffma2(a0, q0.x, wd);
                    ffma2(a1, q0.y, wd);
                    ffma2(a2, q1.x, wd);
                    ffma2(a3, q1.y, wd);
                }
                a0 = addx2(a0, __shfl_xor_sync(0xffffffffu, a0, 1));
                a1 = addx2(a1, __shfl_xor_sync(0xffffffffu, a1, 1));
                a2 = addx2(a2, __shfl_xor_sync(0xffffffffu, a2, 1));
                a3 = addx2(a3, __shfl_xor_sync(0xffffffffu, a3, 1));
                a0 = addx2(a0, __shfl_xor_sync(0xffffffffu, a0, 2));
                a1 = addx2(a1, __shfl_xor_sync(0xffffffffu, a1, 2));
                a2 = addx2(a2, __shfl_xor_sync(0xffffffffu, a2, 2));
                a3 = addx2(a3, __shfl_xor_sync(0xffffffffu, a3, 2));
            }
            if (sub == 0) {
                float2 p0 = unpk(a0), p1 = unpk(a1), p2 = unpk(a2), p3 = unpk(a3);
                float4 v0, v1;
                v0.x = p0.x + gxnA[0]; v0.y = p0.y + gxnA[1];
                v0.z = p1.x + gxnA[2]; v0.w = p1.y + gxnA[3];
                v1.x = p2.x + gxnA[4]; v1.y = p2.y + gxnA[5];
                v1.z = p3.x + gxnA[6]; v1.w = p3.y + gxnA[7];
                *(float4*)&gA_sm[row * 8] = v0;
                *(float4*)&gA_sm[row * 8 + 4] = v1;
            }
            __syncthreads();
            if (tid < 256) {
                int k = tid >> 3;
                int b = tid & 7;
                float gi = gA_sm[(0 * 32 + k) * 8 + b];
                float gf = gA_sm[(1 * 32 + k) * 8 + b];
                float gg = gA_sm[(2 * 32 + k) * 8 + b];
                float go = gA_sm[(3 * 32 + k) * 8 + b];
                float c = cA_sm[tid];
                float cn = sigf(gf) * c + sigf(gi) * tanhf(gg);
                float hv = sigf(go) * tanhf(cn);
                cA_sm[tid] = cn;
                hsp[((size_t)t * BB + b0A + b) * HH + ks + k] = hv;
                __stcg(&d_h2[grpA][par][ks * 8 + tid], hv);
            }
            if (sub == 0 && s + 1 < SS) {
                int tn = dir ? (SS - 2 - s) : (s + 1);
                const float* gxr = gxp + ((size_t)tn * BB + b0A) * G4 + gr;
#pragma unroll
                for (int b = 0; b < 8; b++) gxnA[b] = __ldg(gxr + (size_t)b * G4);
            }
            if (tid < 256) __threadfence();
            __syncthreads();
            if (tid == 0) atomicAdd(&d_ctr[grpA], 1);
        }

        // ================= chain B =================
        {
            unsigned long long a0 = 0ull, a1 = 0ull, a2 = 0ull, a3 = 0ull;
            if (s > 0) {
                if (tid == 0) {
                    int tgt = 8 * s;
                    while (acq_load(&d_ctr[grpB]) < tgt) {}
                }
                __syncthreads();
                {
                    int parp = par ^ 1;
                    float4 v = __ldcg((const float4*)(d_h2[grpB][parp]) + tid);
                    *(float4*)&hB_sm[tid * 4] = v;
                }
                __syncthreads();
                const float* hb = hB_sm + sub * 8;
#pragma unroll
                for (int kk = 0; kk < 64; kk++) {
                    unsigned long long wd = fdup(w_reg[kk]);
                    const ulonglong2* hp = (const ulonglong2*)(hb + kk * 32);
                    ulonglong2 q0 = hp[0];
                    ulonglong2 q1 = hp[1];
                    ffma2(a0, q0.x, wd);
                    ffma2(a1, q0.y, wd);
                    ffma2(a2, q1.x, wd);
                    ffma2(a3, q1.y, wd);
                }
                a0 = addx2(a0, __shfl_xor_sync(0xffffffffu, a0, 1));
                a1 = addx2(a1, __shfl_xor_sync(0xffffffffu, a1, 1));
                a2 = addx2(a2, __shfl_xor_sync(0xffffffffu, a2, 1));
                a3 = addx2(a3, __shfl_xor_sync(0xffffffffu, a3, 1));
                a0 = addx2(a0, __shfl_xor_sync(0xffffffffu, a0, 2));
                a1 = addx2(a1, __shfl_xor_sync(0xffffffffu, a1, 2));
                a2 = addx2(a2, __shfl_xor_sync(0xffffffffu, a2, 2));
                a3 = addx2(a3, __shfl_xor_sync(0xffffffffu, a3, 2));
            }
            if (sub == 0) {
                float2 p0 = unpk(a0), p1 = unpk(a1), p2 = unpk(a2), p3 = unpk(a3);
                float4 v0, v1;
                v0.x = p0.x + gxnB[0]; v0.y = p0.y + gxnB[1];
                v0.z = p1.x + gxnB[2]; v0.w = p1.y + gxnB[3];
                v1.x = p2.x + gxnB[4]; v1.y = p2.y + gxnB[5];
                v1.z = p3.x + gxnB[6]; v1.w = p3.y + gxnB[7];
                *(float4*)&gB_sm[row * 8] = v0;
                *(float4*)&gB_sm[row * 8 + 4] = v1;
            }
            __syncthreads();
            if (tid < 256) {
                int k = tid >> 3;
                int b = tid & 7;
                float gi = gB_sm[(0 * 32 + k) * 8 + b];
                float gf = gB_sm[(1 * 32 + k) * 8 + b];
                float gg = gB_sm[(2 * 32 + k) * 8 + b];
                float go = gB_sm[(3 * 32 + k) * 8 + b];
                float c = cB_sm[tid];
                float cn = sigf(gf) * c + sigf(gi) * tanhf(gg);
                float hv = sigf(go) * tanhf(cn);
                cB_sm[tid] = cn;
                hsp[((size_t)t * BB + b0B + b) * HH + ks + k] = hv;
                __stcg(&d_h2[grpB][par][ks * 8 + tid], hv);
            }
            if (sub == 0 && s + 1 < SS) {
                int tn = dir ? (SS - 2 - s) : (s + 1);
                const float* gxr = gxp + ((size_t)tn * BB + b0B) * G4 + gr;
#pragma unroll
                for (int b = 0; b < 8; b++) gxnB[b] = __ldg(gxr + (size_t)b * G4);
            }
            if (tid < 256) __threadfence();
            __syncthreads();
            if (tid == 0) atomicAdd(&d_ctr[grpB], 1);
        }
    }
}

// ---------------- emissions: concat(hs_f, hs_b) @ cls_w^T + cls_b ----------------
__global__ void __launch_bounds__(256) k_emis(const float* __restrict__ clsw,
                                              const float* __restrict__ clsb) {
    __shared__ float cw[TT * 512];
    __shared__ float cb[32];
    int tid = threadIdx.x;
    for (int i = tid; i < TT * 512; i += 256) cw[i] = clsw[i];
    if (tid < TT) cb[tid] = clsb[tid];
    __syncthreads();

    int warp = tid >> 5, lane = tid & 31;
    int w = blockIdx.x * 8 + warp;
    int b = w >> 9, s = w & 511;
    const float* hf = d_hs[0] + ((size_t)s * BB + b) * HH;
    const float* hb = d_hs[1] + ((size_t)s * BB + b) * HH;
    float hv[16];
#pragma unroll
    for (int i = 0; i < 8; i++) {
        hv[i] = hf[lane + 32 * i];
        hv[8 + i] = hb[lane + 32 * i];
    }
#pragma unroll 1
    for (int o = 0; o < TT; o++) {
        const float* c0 = cw + o * 512;
        float sum = 0.f;
#pragma unroll
        for (int i = 0; i < 8; i++) {
            sum = fmaf(hv[i], c0[lane + 32 * i], sum);
            sum = fmaf(hv[8 + i], c0[256 + lane + 32 * i], sum);
        }
#pragma unroll
        for (int off = 16; off > 0; off >>= 1)
            sum += __shfl_down_sync(0xffffffffu, sum, off);
        if (lane == 0) d_emis[(size_t)w * TT + o] = sum + cb[o];
    }
}

// ---------------- CRF: blocks 0..63 = loss forward, 64..127 = Viterbi decode -------
__global__ void __launch_bounds__(32) k_crf(const int* __restrict__ labels,
                                            const int* __restrict__ mask,
                                            const float* __restrict__ startt,
                                            const float* __restrict__ endt,
                                            const float* __restrict__ trans,
                                            float* __restrict__ tok_out) {
    int which = blockIdx.x >> 6;
    int b = blockIdx.x & 63;
    int ln = threadIdx.x;
    __shared__ float tr[TT * TT];
    __shared__ float al[TT];
    __shared__ unsigned char bp[SS - 1][TT];
    for (int i = ln; i < TT * TT; i += 32) tr[i] = trans[i];
    __syncwarp();

    if (which == 0) {
        // ---- loss ----
        float part = 0.f;
        for (int s = ln; s < SS; s += 32) {
            int tg = labels[(size_t)b * SS + s];
            float mf = (float)mask[(size_t)b * SS + s];
            part += d_emis[((size_t)b * SS + s) * TT + tg] * mf;
            if (s >= 1) {
                int tp = labels[(size_t)b * SS + s - 1];
                part += tr[tp * TT + tg] * mf;
            }
        }
#pragma unroll
        for (int off = 16; off > 0; off >>= 1)
            part += __shfl_down_sync(0xffffffffu, part, off);
        float num = 0.f;
        if (ln == 0) {
            num = part + startt[labels[(size_t)b * SS]];
            int cnt = 0;
            for (int s = 0; s < SS; s++) cnt += mask[(size_t)b * SS + s];
            num += endt[labels[(size_t)b * SS + cnt - 1]];
        }

        if (ln < TT) al[ln] = startt[ln] + d_emis[((size_t)b * SS) * TT + ln];
        __syncwarp();
        for (int s = 1; s < SS; s++) {
            int m = mask[(size_t)b * SS + s];
            float nv = 0.f;
            if (ln < TT) {
                float v[TT];
                float mx = -1e30f;
#pragma unroll
                for (int i = 0; i < TT; i++) {
                    v[i] = al[i] + tr[i * TT + ln];
                    mx = fmaxf(mx, v[i]);
                }
                float sum = 0.f;
#pragma unroll
                for (int i = 0; i < TT; i++) sum += expf(v[i] - mx);
                nv = mx + logf(sum) + d_emis[((size_t)b * SS + s) * TT + ln];
            }
            __syncwarp();
            if (ln < TT && m > 0) al[ln] = nv;
            __syncwarp();
        }
        if (ln == 0) {
            float mx = -1e30f;
            for (int j = 0; j < TT; j++) mx = fmaxf(mx, al[j] + endt[j]);
            float sum = 0.f;
            for (int j = 0; j < TT; j++) sum += expf(al[j] + endt[j] - mx);
            d_nd[b] = num - (mx + logf(sum));
        }
    } else {
        // ---- Viterbi decode ----
        if (ln < TT) al[ln] = startt[ln] + d_emis[((size_t)b * SS) * TT + ln];
        __syncwarp();
        for (int s = 1; s < SS; s++) {
            int m = mask[(size_t)b * SS + s];
            float nv = 0.f;
            int arg = 0;
            if (ln < TT) {
                float mx = -1e30f;
#pragma unroll
                for (int i = 0; i < TT; i++) {
                    float v = al[i] + tr[i * TT + ln];
                    if (v > mx) { mx = v; arg = i; }
                }
                nv = mx + d_emis[((size_t)b * SS + s) * TT + ln];
            }
            __syncwarp();
            if (ln < TT) {
                if (m > 0) { al[ln] = nv; bp[s - 1][ln] = (unsigned char)arg; }
                else bp[s - 1][ln] = (unsigned char)ln;
            }
            __syncwarp();
        }
        if (ln == 0) {
            float mx = -1e30f;
            int lt = 0;
            for (int j = 0; j < TT; j++) {
                float v = al[j] + endt[j];
                if (v > mx) { mx = v; lt = j; }
            }
            tok_out[(size_t)b * SS + (SS - 1)] = (float)lt;
            int tg = lt;
            for (int s = SS - 2; s >= 0; s--) {
                tg = bp[s][tg];
                tok_out[(size_t)b * SS + s] = (float)tg;
            }
        }
    }
}

// ---------------- final loss reduce ----------------
__global__ void __launch_bounds__(64) k_final(float* __restrict__ out) {
    int tid = threadIdx.x;
    float v = d_nd[tid];
#pragma unroll
    for (int off = 16; off > 0; off >>= 1) v += __shfl_down_sync(0xffffffffu, v, off);
    __shared__ float w[2];
    if ((tid & 31) == 0) w[tid >> 5] = v;
    __syncthreads();
    if (tid == 0) out[0] = -(w[0] + w[1]) / (float)BB;
}

// ---------------- launch ----------------
extern "C" void kernel_launch(void* const* d_in, const int* in_sizes, int n_in,
                              void* d_out, int out_size) {
    const int* tok     = (const int*)d_in[0];
    const int* ctok    = (const int*)d_in[1];
    const int* labels  = (const int*)d_in[2];
    const int* amask   = (const int*)d_in[3];
    const float* wemb  = (const float*)d_in[4];
    const float* cemb  = (const float*)d_in[5];
    const float* convw = (const float*)d_in[6];
    const float* convb = (const float*)d_in[7];
    const float* wihf  = (const float*)d_in[8];
    const float* whhf  = (const float*)d_in[9];
    const float* bf    = (const float*)d_in[10];
    const float* wihb  = (const float*)d_in[11];
    const float* whhb  = (const float*)d_in[12];
    const float* bb    = (const float*)d_in[13];
    const float* clsw  = (const float*)d_in[14];
    const float* clsb  = (const float*)d_in[15];
    const float* startt = (const float*)d_in[16];
    const float* endt   = (const float*)d_in[17];
    const float* trans  = (const float*)d_in[18];
    float* out = (float*)d_out;
    int tok_off = out_size - BB * SS;
    if (tok_off < 0) tok_off = 0;

    k_init<<<1, 32>>>();
    k_embed<<<BS, 128>>>(tok, ctok, wemb, cemb, convw, convb);
    dim3 gg(BS / 128, G4 / 64, 2);
    k_gemm_gx<<<gg, 256>>>(wihf, bf, wihb, bb);
    k_lstm<<<64, 512>>>(whhf, whhb);
    k_emis<<<BS / 8, 256>>>(clsw, clsb);
    k_crf<<<2 * BB, 32>>>(labels, amask, startt, endt, trans, out + tok_off);
    k_final<<<1, 64>>>(out);
}

// round 10
// speedup vs baseline: 1.0690x; 1.0690x over previous
#include <cuda_runtime.h>
#include <math.h>
#include <stdint.h>

#define BB 64
#define SS 512
#define BS (BB*SS)
#define LL 16
#define WD 200
#define CD 30
#define FN 4
#define CF 120
#define KW 3
#define DD 320
#define HH 256
#define G4 1024
#define TT 17
#define LC 14

// ---------------- static scratch (no allocs allowed) ----------------
__device__ float d_z[BS * DD];                    // [B*S, 320]
__device__ float d_gx[2][(size_t)SS * BB * G4];   // [dir][S,B,1024]
__device__ float d_hs[2][(size_t)SS * BB * HH];   // [dir][S,B,256]
__device__ float d_h2[16][2][HH * 8];             // [grp][parity][k*8+b] h exchange
__device__ float d_emis[(size_t)BS * TT];         // [B,S,17]
__device__ float d_nd[BB];
__device__ int   d_flag[16][8];                   // [grp][slice] release/acquire flags

__device__ __forceinline__ float sigf(float x) { return 1.0f / (1.0f + expf(-x)); }

__device__ __forceinline__ int acq_load(const int* p) {
    int v;
    asm volatile("ld.global.acquire.gpu.b32 %0,[%1];" : "=r"(v) : "l"(p) : "memory");
    return v;
}
__device__ __forceinline__ void rel_store(int* p, int v) {
    asm volatile("st.global.release.gpu.b32 [%0],%1;" :: "l"(p), "r"(v) : "memory");
}

// ---- packed f32x2 helpers (sm_103a FFMA2) ----
__device__ __forceinline__ unsigned long long fdup(float w) {
    unsigned long long d;
    asm("mov.b64 %0, {%1, %1};" : "=l"(d) : "f"(w));
    return d;
}
__device__ __forceinline__ void ffma2(unsigned long long& a, unsigned long long x,
                                      unsigned long long y) {
    asm("fma.rn.f32x2 %0, %1, %2, %0;" : "+l"(a) : "l"(x), "l"(y));
}
__device__ __forceinline__ unsigned long long addx2(unsigned long long a,
                                                    unsigned long long b) {
    unsigned long long r;
    asm("add.rn.f32x2 %0, %1, %2;" : "=l"(r) : "l"(a), "l"(b));
    return r;
}
__device__ __forceinline__ float2 unpk(unsigned long long a) {
    float2 f;
    asm("mov.b64 {%0, %1}, %2;" : "=f"(f.x), "=f"(f.y) : "l"(a));
    return f;
}

// ---------------- init (reset flags each launch) ----------------
__global__ void k_init() {
    int t = threadIdx.x;
    if (t < 128) ((int*)d_flag)[t] = 0;
}

// ---------------- embeddings + char CNN + concat ----------------
__global__ void __launch_bounds__(128) k_embed(const int* __restrict__ tok,
                                               const int* __restrict__ ctok,
                                               const float* __restrict__ wemb,
                                               const float* __restrict__ cemb,
                                               const float* __restrict__ convw,
                                               const float* __restrict__ convb) {
    int w = blockIdx.x;  // word = b*S + s
    __shared__ float ce[LL][CD];
    __shared__ int cid[LL];
    int tid = threadIdx.x;
    if (tid < LL) cid[tid] = ctok[(size_t)w * LL + tid];
    __syncthreads();
    for (int i = tid; i < LL * CD; i += 128) {
        int l = i / CD, c = i % CD;
        ce[l][c] = cemb[cid[l] * CD + c];
    }
    __syncthreads();
    if (tid < CF) {
        int o = tid, ic = o >> 2;
        float w0 = convw[o * 3 + 0], w1 = convw[o * 3 + 1], w2 = convw[o * 3 + 2];
        float m = -1e30f;
#pragma unroll
        for (int t = 0; t < LC; t++) {
            float v = ce[t][ic] * w0 + ce[t + 1][ic] * w1 + ce[t + 2][ic] * w2;
            m = fmaxf(m, v);
        }
        d_z[(size_t)w * DD + WD + o] = m + convb[o];
    }
    const float* wr = wemb + (size_t)tok[w] * WD;
    for (int j = tid; j < WD; j += 128) d_z[(size_t)w * DD + j] = wr[j];
}

// ---------------- input-side GEMM with FFMA2: z[BS,320] @ W^T -> gx ----------------
__global__ void __launch_bounds__(256, 2) k_gemm_gx(const float* __restrict__ Wf,
                                                    const float* __restrict__ biasf,
                                                    const float* __restrict__ Wb,
                                                    const float* __restrict__ biasb) {
    int dir = blockIdx.z;
    const float* __restrict__ Wm = dir ? Wb : Wf;
    const float* __restrict__ bias = dir ? biasb : biasf;
    float* out = d_gx[dir];
    const float* __restrict__ Z = d_z;

    int mBase = blockIdx.x * 128;
    int nBase = blockIdx.y * 64;

    __shared__ float As[16][132];
    __shared__ float Bs[16][68];

    int tid = threadIdx.x;
    int ty = tid >> 4;
    int tx = tid & 15;

    unsigned long long acc2[8][2];
#pragma unroll
    for (int i = 0; i < 8; i++) { acc2[i][0] = 0ull; acc2[i][1] = 0ull; }

    for (int k0 = 0; k0 < DD; k0 += 16) {
#pragma unroll
        for (int r = 0; r < 2; r++) {
            int idx = tid + r * 256;
            int row = idx >> 2, kq = idx & 3;
            float4 v = *(const float4*)&Z[(size_t)(mBase + row) * DD + k0 + kq * 4];
            As[kq * 4 + 0][row] = v.x;
            As[kq * 4 + 1][row] = v.y;
            As[kq * 4 + 2][row] = v.z;
            As[kq * 4 + 3][row] = v.w;
        }
        {
            int row = tid >> 2, kq = tid & 3;
            float4 v = *(const float4*)&Wm[(size_t)(nBase + row) * DD + k0 + kq * 4];
            Bs[kq * 4 + 0][row] = v.x;
            Bs[kq * 4 + 1][row] = v.y;
            Bs[kq * 4 + 2][row] = v.z;
            Bs[kq * 4 + 3][row] = v.w;
        }
        __syncthreads();
#pragma unroll
        for (int kk = 0; kk < 16; kk++) {
            float4 a0 = *(const float4*)&As[kk][ty * 8];
            float4 a1 = *(const float4*)&As[kk][ty * 8 + 4];
            ulonglong2 bq = *(const ulonglong2*)&Bs[kk][tx * 4];
            float av[8] = {a0.x, a0.y, a0.z, a0.w, a1.x, a1.y, a1.z, a1.w};
#pragma unroll
            for (int i = 0; i < 8; i++) {
                unsigned long long ad = fdup(av[i]);
                ffma2(acc2[i][0], bq.x, ad);
                ffma2(acc2[i][1], bq.y, ad);
            }
        }
        __syncthreads();
    }

    float bq0 = bias[nBase + tx * 4 + 0], bq1 = bias[nBase + tx * 4 + 1];
    float bq2 = bias[nBase + tx * 4 + 2], bq3 = bias[nBase + tx * 4 + 3];
#pragma unroll
    for (int i = 0; i < 8; i++) {
        int m = mBase + ty * 8 + i;
        int b = m >> 9, s = m & 511;
        size_t ro = ((size_t)s * BB + b) * (size_t)G4 + nBase + tx * 4;
        float2 p0 = unpk(acc2[i][0]);
        float2 p1 = unpk(acc2[i][1]);
        float4 o4;
        o4.x = p0.x + bq0;
        o4.y = p0.y + bq1;
        o4.z = p1.x + bq2;
        o4.w = p1.y + bq3;
        *(float4*)&out[ro] = o4;
    }
}

// ---------------- BiLSTM: 128 CTAs (16 groups x 8 slices), 512 thr/CTA -------------
// Structure identical to the R6 winner; sync rebuilt on per-producer release flags:
//  producer: cell st.cg stores -> bar.sync -> tid0 st.release flag[grp][slice]=s+1
//  consumer: each thread acquire-polls ONLY flag[grp][tid>>6] (the slice covering
//  its float4), ld.cg's its chunk, one bar.sync, matvec. No threadfence, no atomics.
__global__ void __launch_bounds__(512, 1)
k_lstm(const float* __restrict__ whf, const float* __restrict__ whb) {
    __shared__ float h_sm[HH * 8];       // staged h(s-1) [k*8+b]
    __shared__ float g_sm[128 * 8];      // gates [local row][8 batch]
    __shared__ float c_sm[32 * 8];       // cell state [k*8+b]

    int blk = blockIdx.x;
    int slice = blk & 7;
    int grp = blk >> 3;          // 0..15
    int dir = grp >> 3;
    int bg = grp & 7;
    const float* Wd = dir ? whb : whf;
    int tid = threadIdx.x;
    int row = tid >> 2;          // 0..127 local gate row
    int sub = tid & 3;           // k-interleave lane
    int gt = row >> 5;           // gate 0..3
    int kl = row & 31;
    int ks = slice * 32;
    int gr = gt * 256 + ks + kl; // gate row in [0,1024)
    const float* gxp = d_gx[dir];
    float* hsp = d_hs[dir];
    int b0 = bg * 8;
    int jsl = tid >> 6;          // slice whose data this thread's float4 covers

    // W into registers: w_reg[kk] = W[gr][4*kk + sub]
    float w_reg[64];
    {
        const float* wr = Wd + (size_t)gr * HH + sub;
#pragma unroll
        for (int kk = 0; kk < 64; kk++) w_reg[kk] = __ldg(wr + 4 * kk);
    }
    if (tid < 256) c_sm[tid] = 0.f;
    __syncthreads();

    // preload gx for step 0 (sub==0 threads hold gxn for their row)
    float gxn[8];
    if (sub == 0) {
        int t0 = dir ? (SS - 1) : 0;
        const float* gxr = gxp + ((size_t)t0 * BB + b0) * G4 + gr;
#pragma unroll
        for (int b = 0; b < 8; b++) gxn[b] = __ldg(gxr + (size_t)b * G4);
    }

    for (int s = 0; s < SS; s++) {
        int t = dir ? (SS - 1 - s) : s;
        int par = s & 1;
        unsigned long long a0 = 0ull, a1 = 0ull, a2 = 0ull, a3 = 0ull;

        if (s > 0) {
            // wait only for the slice covering THIS thread's h chunk, then load it
            while (acq_load(&d_flag[grp][jsl]) < s) {}
            {
                int parp = par ^ 1;
                float4 v = __ldcg((const float4*)(d_h2[grp][parp]) + tid);
                *(float4*)&h_sm[tid * 4] = v;
            }
            __syncthreads();

            const float* hb = h_sm + sub * 8;
#pragma unroll
            for (int kk = 0; kk < 64; kk++) {
                unsigned long long wd = fdup(w_reg[kk]);
                const ulonglong2* hp = (const ulonglong2*)(hb + kk * 32);
                ulonglong2 q0 = hp[0];   // batches 0,1 | 2,3
                ulonglong2 q1 = hp[1];   // batches 4,5 | 6,7
                ffma2(a0, q0.x, wd);
                ffma2(a1, q0.y, wd);
                ffma2(a2, q1.x, wd);
                ffma2(a3, q1.y, wd);
            }
            // reduce across the 4 sub lanes (adjacent in warp)
            a0 = addx2(a0, __shfl_xor_sync(0xffffffffu, a0, 1));
            a1 = addx2(a1, __shfl_xor_sync(0xffffffffu, a1, 1));
            a2 = addx2(a2, __shfl_xor_sync(0xffffffffu, a2, 1));
            a3 = addx2(a3, __shfl_xor_sync(0xffffffffu, a3, 1));
            a0 = addx2(a0, __shfl_xor_sync(0xffffffffu, a0, 2));
            a1 = addx2(a1, __shfl_xor_sync(0xffffffffu, a1, 2));
            a2 = addx2(a2, __shfl_xor_sync(0xffffffffu, a2, 2));
            a3 = addx2(a3, __shfl_xor_sync(0xffffffffu, a3, 2));
        }
        if (sub == 0) {
            float2 p0 = unpk(a0), p1 = unpk(a1), p2 = unpk(a2), p3 = unpk(a3);
            float4 v0, v1;
            v0.x = p0.x + gxn[0]; v0.y = p0.y + gxn[1];
            v0.z = p1.x + gxn[2]; v0.w = p1.y + gxn[3];
            v1.x = p2.x + gxn[4]; v1.y = p2.y + gxn[5];
            v1.z = p3.x + gxn[6]; v1.w = p3.y + gxn[7];
            *(float4*)&g_sm[row * 8] = v0;
            *(float4*)&g_sm[row * 8 + 4] = v1;
        }
        __syncthreads();

        // LSTM cell: 256 tasks (k = tid>>3, b = tid&7), store h to L2 exchange buf
        if (tid < 256) {
            int k = tid >> 3;
            int b = tid & 7;
            float gi = g_sm[(0 * 32 + k) * 8 + b];
            float gf = g_sm[(1 * 32 + k) * 8 + b];
            float gg = g_sm[(2 * 32 + k) * 8 + b];
            float go = g_sm[(3 * 32 + k) * 8 + b];
            float c = c_sm[tid];
            float cn = sigf(gf) * c + sigf(gi) * tanhf(gg);
            float hv = sigf(go) * tanhf(cn);
            c_sm[tid] = cn;
            hsp[((size_t)t * BB + b0 + b) * HH + ks + k] = hv;
            __stcg(&d_h2[grp][par][ks * 8 + tid], hv);
        }
        // prefetch next step's gx (independent of the publish)
        if (sub == 0 && s + 1 < SS) {
            int tn = dir ? (SS - 2 - s) : (s + 1);
            const float* gxr = gxp + ((size_t)tn * BB + b0) * G4 + gr;
#pragma unroll
            for (int b = 0; b < 8; b++) gxn[b] = __ldg(gxr + (size_t)b * G4);
        }
        __syncthreads();   // all cell stores issued before the release publish
        if (tid == 0) rel_store(&d_flag[grp][slice], s + 1);
    }
}

// ---------------- emissions: concat(hs_f, hs_b) @ cls_w^T + cls_b ----------------
__global__ void __launch_bounds__(256) k_emis(const float* __restrict__ clsw,
                                              const float* __restrict__ clsb) {
    __shared__ float cw[TT * 512];
    __shared__ float cb[32];
    int tid = threadIdx.x;
    for (int i = tid; i < TT * 512; i += 256) cw[i] = clsw[i];
    if (tid < TT) cb[tid] = clsb[tid];
    __syncthreads();

    int warp = tid >> 5, lane = tid & 31;
    int w = blockIdx.x * 8 + warp;
    int b = w >> 9, s = w & 511;
    const float* hf = d_hs[0] + ((size_t)s * BB + b) * HH;
    const float* hb = d_hs[1] + ((size_t)s * BB + b) * HH;
    float hv[16];
#pragma unroll
    for (int i = 0; i < 8; i++) {
        hv[i] = hf[lane + 32 * i];
        hv[8 + i] = hb[lane + 32 * i];
    }
#pragma unroll 1
    for (int o = 0; o < TT; o++) {
        const float* c0 = cw + o * 512;
        float sum = 0.f;
#pragma unroll
        for (int i = 0; i < 8; i++) {
            sum = fmaf(hv[i], c0[lane + 32 * i], sum);
            sum = fmaf(hv[8 + i], c0[256 + lane + 32 * i], sum);
        }
#pragma unroll
        for (int off = 16; off > 0; off >>= 1)
            sum += __shfl_down_sync(0xffffffffu, sum, off);
        if (lane == 0) d_emis[(size_t)w * TT + o] = sum + cb[o];
    }
}

// ---------------- CRF: blocks 0..63 = loss forward, 64..127 = Viterbi decode -------
__global__ void __launch_bounds__(32) k_crf(const int* __restrict__ labels,
                                            const int* __restrict__ mask,
                                            const float* __restrict__ startt,
                                            const float* __restrict__ endt,
                                            const float* __restrict__ trans,
                                            float* __restrict__ tok_out) {
    int which = blockIdx.x >> 6;
    int b = blockIdx.x & 63;
    int ln = threadIdx.x;
    __shared__ float tr[TT * TT];
    __shared__ float al[TT];
    __shared__ unsigned char bp[SS - 1][TT];
    for (int i = ln; i < TT * TT; i += 32) tr[i] = trans[i];
    __syncwarp();

    if (which == 0) {
        // ---- loss ----
        float part = 0.f;
        for (int s = ln; s < SS; s += 32) {
            int tg = labels[(size_t)b * SS + s];
            float mf = (float)mask[(size_t)b * SS + s];
            part += d_emis[((size_t)b * SS + s) * TT + tg] * mf;
            if (s >= 1) {
                int tp = labels[(size_t)b * SS + s - 1];
                part += tr[tp * TT + tg] * mf;
            }
        }
#pragma unroll
        for (int off = 16; off > 0; off >>= 1)
            part += __shfl_down_sync(0xffffffffu, part, off);
        float num = 0.f;
        if (ln == 0) {
            num = part + startt[labels[(size_t)b * SS]];
            int cnt = 0;
            for (int s = 0; s < SS; s++) cnt += mask[(size_t)b * SS + s];
            num += endt[labels[(size_t)b * SS + cnt - 1]];
        }

        if (ln < TT) al[ln] = startt[ln] + d_emis[((size_t)b * SS) * TT + ln];
        __syncwarp();
        for (int s = 1; s < SS; s++) {
            int m = mask[(size_t)b * SS + s];
            float nv = 0.f;
            if (ln < TT) {
                float v[TT];
                float mx = -1e30f;
#pragma unroll
                for (int i = 0; i < TT; i++) {
                    v[i] = al[i] + tr[i * TT + ln];
                    mx = fmaxf(mx, v[i]);
                }
                float sum = 0.f;
#pragma unroll
                for (int i = 0; i < TT; i++) sum += expf(v[i] - mx);
                nv = mx + logf(sum) + d_emis[((size_t)b * SS + s) * TT + ln];
            }
            __syncwarp();
            if (ln < TT && m > 0) al[ln] = nv;
            __syncwarp();
        }
        if (ln == 0) {
            float mx = -1e30f;
            for (int j = 0; j < TT; j++) mx = fmaxf(mx, al[j] + endt[j]);
            float sum = 0.f;
            for (int j = 0; j < TT; j++) sum += expf(al[j] + endt[j] - mx);
            d_nd[b] = num - (mx + logf(sum));
        }
    } else {
        // ---- Viterbi decode ----
        if (ln < TT) al[ln] = startt[ln] + d_emis[((size_t)b * SS) * TT + ln];
        __syncwarp();
        for (int s = 1; s < SS; s++) {
            int m = mask[(size_t)b * SS + s];
            float nv = 0.f;
            int arg = 0;
            if (ln < TT) {
                float mx = -1e30f;
#pragma unroll
                for (int i = 0; i < TT; i++) {
                    float v = al[i] + tr[i * TT + ln];
                    if (v > mx) { mx = v; arg = i; }
                }
                nv = mx + d_emis[((size_t)b * SS + s) * TT + ln];
            }
            __syncwarp();
            if (ln < TT) {
                if (m > 0) { al[ln] = nv; bp[s - 1][ln] = (unsigned char)arg; }
                else bp[s - 1][ln] = (unsigned char)ln;
            }
            __syncwarp();
        }
        if (ln == 0) {
            float mx = -1e30f;
            int lt = 0;
            for (int j = 0; j < TT; j++) {
                float v = al[j] + endt[j];
                if (v > mx) { mx = v; lt = j; }
            }
            tok_out[(size_t)b * SS + (SS - 1)] = (float)lt;
            int tg = lt;
            for (int s = SS - 2; s >= 0; s--) {
                tg = bp[s][tg];
                tok_out[(size_t)b * SS + s] = (float)tg;
            }
        }
    }
}

// ---------------- final loss reduce ----------------
__global__ void __launch_bounds__(64) k_final(float* __restrict__ out) {
    int tid = threadIdx.x;
    float v = d_nd[tid];
#pragma unroll
    for (int off = 16; off > 0; off >>= 1) v += __shfl_down_sync(0xffffffffu, v, off);
    __shared__ float w[2];
    if ((tid & 31) == 0) w[tid >> 5] = v;
    __syncthreads();
    if (tid == 0) out[0] = -(w[0] + w[1]) / (float)BB;
}

// ---------------- launch ----------------
extern "C" void kernel_launch(void* const* d_in, const int* in_sizes, int n_in,
                              void* d_out, int out_size) {
    const int* tok     = (const int*)d_in[0];
    const int* ctok    = (const int*)d_in[1];
    const int* labels  = (const int*)d_in[2];
    const int* amask   = (const int*)d_in[3];
    const float* wemb  = (const float*)d_in[4];
    const float* cemb  = (const float*)d_in[5];
    const float* convw = (const float*)d_in[6];
    const float* convb = (const float*)d_in[7];
    const float* wihf  = (const float*)d_in[8];
    const float* whhf  = (const float*)d_in[9];
    const float* bf    = (const float*)d_in[10];
    const float* wihb  = (const float*)d_in[11];
    const float* whhb  = (const float*)d_in[12];
    const float* bb    = (const float*)d_in[13];
    const float* clsw  = (const float*)d_in[14];
    const float* clsb  = (const float*)d_in[15];
    const float* startt = (const float*)d_in[16];
    const float* endt   = (const float*)d_in[17];
    const float* trans  = (const float*)d_in[18];
    float* out = (float*)d_out;
    int tok_off = out_size - BB * SS;
    if (tok_off < 0) tok_off = 0;

    k_init<<<1, 128>>>();
    k_embed<<<BS, 128>>>(tok, ctok, wemb, cemb, convw, convb);
    dim3 gg(BS / 128, G4 / 64, 2);
    k_gemm_gx<<<gg, 256>>>(wihf, bf, wihb, bb);
    k_lstm<<<128, 512>>>(whhf, whhb);
    k_emis<<<BS / 8, 256>>>(clsw, clsb);
    k_crf<<<2 * BB, 32>>>(labels, amask, startt, endt, trans, out + tok_off);
    k_final<<<1, 64>>>(out);
}

// round 11
// speedup vs baseline: 1.2549x; 1.1740x over previous
#include <cuda_runtime.h>
#include <math.h>
#include <stdint.h>

#define BB 64
#define SS 512
#define BS (BB*SS)
#define LL 16
#define WD 200
#define CD 30
#define FN 4
#define CF 120
#define KW 3
#define DD 320
#define HH 256
#define G4 1024
#define TT 17
#define LC 14

// ---------------- static scratch (no allocs allowed) ----------------
__device__ float d_z[BS * DD];                    // [B*S, 320]
__device__ float d_gx[2][(size_t)SS * BB * G4];   // [dir][S,B,1024]
__device__ float d_hs[2][(size_t)SS * BB * HH];   // [dir][S,B,256]
__device__ float d_h2[16][2][HH * 8];             // [grp][parity][k*8+b] h exchange
__device__ float d_emis[(size_t)BS * TT];         // [B,S,17]
__device__ float d_nd[BB];
__device__ int   d_flag[16][8];                   // [grp][slice] release flags (one 32B sector per grp)

__device__ __forceinline__ float sigf(float x) { return 1.0f / (1.0f + expf(-x)); }

__device__ __forceinline__ int acq_load(const int* p) {
    int v;
    asm volatile("ld.global.acquire.gpu.b32 %0,[%1];" : "=r"(v) : "l"(p) : "memory");
    return v;
}
__device__ __forceinline__ void rel_store(int* p, int v) {
    asm volatile("st.global.release.gpu.b32 [%0],%1;" :: "l"(p), "r"(v) : "memory");
}

// ---- packed f32x2 helpers (sm_103a FFMA2) ----
__device__ __forceinline__ unsigned long long fdup(float w) {
    unsigned long long d;
    asm("mov.b64 %0, {%1, %1};" : "=l"(d) : "f"(w));
    return d;
}
__device__ __forceinline__ void ffma2(unsigned long long& a, unsigned long long x,
                                      unsigned long long y) {
    asm("fma.rn.f32x2 %0, %1, %2, %0;" : "+l"(a) : "l"(x), "l"(y));
}
__device__ __forceinline__ unsigned long long addx2(unsigned long long a,
                                                    unsigned long long b) {
    unsigned long long r;
    asm("add.rn.f32x2 %0, %1, %2;" : "=l"(r) : "l"(a), "l"(b));
    return r;
}
__device__ __forceinline__ float2 unpk(unsigned long long a) {
    float2 f;
    asm("mov.b64 {%0, %1}, %2;" : "=f"(f.x), "=f"(f.y) : "l"(a));
    return f;
}

// ---------------- init (reset flags each launch) ----------------
__global__ void k_init() {
    int t = threadIdx.x;
    if (t < 128) ((int*)d_flag)[t] = 0;
}

// ---------------- embeddings + char CNN + concat ----------------
__global__ void __launch_bounds__(128) k_embed(const int* __restrict__ tok,
                                               const int* __restrict__ ctok,
                                               const float* __restrict__ wemb,
                                               const float* __restrict__ cemb,
                                               const float* __restrict__ convw,
                                               const float* __restrict__ convb) {
    int w = blockIdx.x;  // word = b*S + s
    __shared__ float ce[LL][CD];
    __shared__ int cid[LL];
    int tid = threadIdx.x;
    if (tid < LL) cid[tid] = ctok[(size_t)w * LL + tid];
    __syncthreads();
    for (int i = tid; i < LL * CD; i += 128) {
        int l = i / CD, c = i % CD;
        ce[l][c] = cemb[cid[l] * CD + c];
    }
    __syncthreads();
    if (tid < CF) {
        int o = tid, ic = o >> 2;
        float w0 = convw[o * 3 + 0], w1 = convw[o * 3 + 1], w2 = convw[o * 3 + 2];
        float m = -1e30f;
#pragma unroll
        for (int t = 0; t < LC; t++) {
            float v = ce[t][ic] * w0 + ce[t + 1][ic] * w1 + ce[t + 2][ic] * w2;
            m = fmaxf(m, v);
        }
        d_z[(size_t)w * DD + WD + o] = m + convb[o];
    }
    const float* wr = wemb + (size_t)tok[w] * WD;
    for (int j = tid; j < WD; j += 128) d_z[(size_t)w * DD + j] = wr[j];
}

// ---------------- input-side GEMM with FFMA2: z[BS,320] @ W^T -> gx ----------------
__global__ void __launch_bounds__(256, 2) k_gemm_gx(const float* __restrict__ Wf,
                                                    const float* __restrict__ biasf,
                                                    const float* __restrict__ Wb,
                                                    const float* __restrict__ biasb) {
    int dir = blockIdx.z;
    const float* __restrict__ Wm = dir ? Wb : Wf;
    const float* __restrict__ bias = dir ? biasb : biasf;
    float* out = d_gx[dir];
    const float* __restrict__ Z = d_z;

    int mBase = blockIdx.x * 128;
    int nBase = blockIdx.y * 64;

    __shared__ float As[16][132];
    __shared__ float Bs[16][68];

    int tid = threadIdx.x;
    int ty = tid >> 4;
    int tx = tid & 15;

    unsigned long long acc2[8][2];
#pragma unroll
    for (int i = 0; i < 8; i++) { acc2[i][0] = 0ull; acc2[i][1] = 0ull; }

    for (int k0 = 0; k0 < DD; k0 += 16) {
#pragma unroll
        for (int r = 0; r < 2; r++) {
            int idx = tid + r * 256;
            int row = idx >> 2, kq = idx & 3;
            float4 v = *(const float4*)&Z[(size_t)(mBase + row) * DD + k0 + kq * 4];
            As[kq * 4 + 0][row] = v.x;
            As[kq * 4 + 1][row] = v.y;
            As[kq * 4 + 2][row] = v.z;
            As[kq * 4 + 3][row] = v.w;
        }
        {
            int row = tid >> 2, kq = tid & 3;
            float4 v = *(const float4*)&Wm[(size_t)(nBase + row) * DD + k0 + kq * 4];
            Bs[kq * 4 + 0][row] = v.x;
            Bs[kq * 4 + 1][row] = v.y;
            Bs[kq * 4 + 2][row] = v.z;
            Bs[kq * 4 + 3][row] = v.w;
        }
        __syncthreads();
#pragma unroll
        for (int kk = 0; kk < 16; kk++) {
            float4 a0 = *(const float4*)&As[kk][ty * 8];
            float4 a1 = *(const float4*)&As[kk][ty * 8 + 4];
            ulonglong2 bq = *(const ulonglong2*)&Bs[kk][tx * 4];
            float av[8] = {a0.x, a0.y, a0.z, a0.w, a1.x, a1.y, a1.z, a1.w};
#pragma unroll
            for (int i = 0; i < 8; i++) {
                unsigned long long ad = fdup(av[i]);
                ffma2(acc2[i][0], bq.x, ad);
                ffma2(acc2[i][1], bq.y, ad);
            }
        }
        __syncthreads();
    }

    float bq0 = bias[nBase + tx * 4 + 0], bq1 = bias[nBase + tx * 4 + 1];
    float bq2 = bias[nBase + tx * 4 + 2], bq3 = bias[nBase + tx * 4 + 3];
#pragma unroll
    for (int i = 0; i < 8; i++) {
        int m = mBase + ty * 8 + i;
        int b = m >> 9, s = m & 511;
        size_t ro = ((size_t)s * BB + b) * (size_t)G4 + nBase + tx * 4;
        float2 p0 = unpk(acc2[i][0]);
        float2 p1 = unpk(acc2[i][1]);
        float4 o4;
        o4.x = p0.x + bq0;
        o4.y = p0.y + bq1;
        o4.z = p1.x + bq2;
        o4.w = p1.y + bq3;
        *(float4*)&out[ro] = o4;
    }
}

// ---------------- BiLSTM: 128 CTAs (16 groups x 8 slices), 512 thr/CTA -------------
// R6 structure; sync = per-producer release flag + single-poller (tid0) acquire scan.
// Producer: cell st.cg stores -> bar.sync -> tid0 st.release flag[grp][slice]=s+1
//           (bar gives intra-CTA hb; release publishes the h2 stores; no MEMBAR,
//            no atomics). d_hs history write moved AFTER publish (off crit path).
// Consumer: tid0 polls all 8 flags (one 32B sector -> one pipelined L2 round per
//           poll), bar.sync, ldcg h, bar.sync, matvec.
__global__ void __launch_bounds__(512, 1)
k_lstm(const float* __restrict__ whf, const float* __restrict__ whb) {
    __shared__ float h_sm[HH * 8];       // staged h(s-1) [k*8+b]
    __shared__ float g_sm[128 * 8];      // gates [local row][8 batch]
    __shared__ float c_sm[32 * 8];       // cell state [k*8+b]

    int blk = blockIdx.x;
    int slice = blk & 7;
    int grp = blk >> 3;          // 0..15
    int dir = grp >> 3;
    int bg = grp & 7;
    const float* Wd = dir ? whb : whf;
    int tid = threadIdx.x;
    int row = tid >> 2;          // 0..127 local gate row
    int sub = tid & 3;           // k-interleave lane
    int gt = row >> 5;           // gate 0..3
    int kl = row & 31;
    int ks = slice * 32;
    int gr = gt * 256 + ks + kl; // gate row in [0,1024)
    const float* gxp = d_gx[dir];
    float* hsp = d_hs[dir];
    int b0 = bg * 8;

    // W into registers: w_reg[kk] = W[gr][4*kk + sub]
    float w_reg[64];
    {
        const float* wr = Wd + (size_t)gr * HH + sub;
#pragma unroll
        for (int kk = 0; kk < 64; kk++) w_reg[kk] = __ldg(wr + 4 * kk);
    }
    if (tid < 256) c_sm[tid] = 0.f;
    __syncthreads();

    // preload gx for step 0 (sub==0 threads hold gxn for their row)
    float gxn[8];
    if (sub == 0) {
        int t0 = dir ? (SS - 1) : 0;
        const float* gxr = gxp + ((size_t)t0 * BB + b0) * G4 + gr;
#pragma unroll
        for (int b = 0; b < 8; b++) gxn[b] = __ldg(gxr + (size_t)b * G4);
    }

    for (int s = 0; s < SS; s++) {
        int t = dir ? (SS - 1 - s) : s;
        int par = s & 1;
        unsigned long long a0 = 0ull, a1 = 0ull, a2 = 0ull, a3 = 0ull;

        if (s > 0) {
            // single poller scans the group's 8 flags (same 32B sector)
            if (tid == 0) {
                const int* f = d_flag[grp];
                for (;;) {
                    int ok = 1;
#pragma unroll
                    for (int j = 0; j < 8; j++) ok &= (acq_load(&f[j]) >= s);
                    if (ok) break;
                }
            }
            __syncthreads();
            {
                int parp = par ^ 1;
                float4 v = __ldcg((const float4*)(d_h2[grp][parp]) + tid);
                *(float4*)&h_sm[tid * 4] = v;
            }
            __syncthreads();

            const float* hb = h_sm + sub * 8;
#pragma unroll
            for (int kk = 0; kk < 64; kk++) {
                unsigned long long wd = fdup(w_reg[kk]);
                const ulonglong2* hp = (const ulonglong2*)(hb + kk * 32);
                ulonglong2 q0 = hp[0];   // batches 0,1 | 2,3
                ulonglong2 q1 = hp[1];   // batches 4,5 | 6,7
                ffma2(a0, q0.x, wd);
                ffma2(a1, q0.y, wd);
                ffma2(a2, q1.x, wd);
                ffma2(a3, q1.y, wd);
            }
            // reduce across the 4 sub lanes (adjacent in warp)
            a0 = addx2(a0, __shfl_xor_sync(0xffffffffu, a0, 1));
            a1 = addx2(a1, __shfl_xor_sync(0xffffffffu, a1, 1));
            a2 = addx2(a2, __shfl_xor_sync(0xffffffffu, a2, 1));
            a3 = addx2(a3, __shfl_xor_sync(0xffffffffu, a3, 1));
            a0 = addx2(a0, __shfl_xor_sync(0xffffffffu, a0, 2));
            a1 = addx2(a1, __shfl_xor_sync(0xffffffffu, a1, 2));
            a2 = addx2(a2, __shfl_xor_sync(0xffffffffu, a2, 2));
            a3 = addx2(a3, __shfl_xor_sync(0xffffffffu, a3, 2));
        }
        if (sub == 0) {
            float2 p0 = unpk(a0), p1 = unpk(a1), p2 = unpk(a2), p3 = unpk(a3);
            float4 v0, v1;
            v0.x = p0.x + gxn[0]; v0.y = p0.y + gxn[1];
            v0.z = p1.x + gxn[2]; v0.w = p1.y + gxn[3];
            v1.x = p2.x + gxn[4]; v1.y = p2.y + gxn[5];
            v1.z = p3.x + gxn[6]; v1.w = p3.y + gxn[7];
            *(float4*)&g_sm[row * 8] = v0;
            *(float4*)&g_sm[row * 8 + 4] = v1;
        }
        __syncthreads();

        // LSTM cell: 256 tasks (k = tid>>3, b = tid&7); publish-critical store only
        float hv = 0.f;
        if (tid < 256) {
            int k = tid >> 3;
            int b = tid & 7;
            float gi = g_sm[(0 * 32 + k) * 8 + b];
            float gf = g_sm[(1 * 32 + k) * 8 + b];
            float gg = g_sm[(2 * 32 + k) * 8 + b];
            float go = g_sm[(3 * 32 + k) * 8 + b];
            float c = c_sm[tid];
            float cn = sigf(gf) * c + sigf(gi) * tanhf(gg);
            hv = sigf(go) * tanhf(cn);
            c_sm[tid] = cn;
            __stcg(&d_h2[grp][par][ks * 8 + tid], hv);
        }
        // prefetch next step's gx (independent of the publish)
        if (sub == 0 && s + 1 < SS) {
            int tn = dir ? (SS - 2 - s) : (s + 1);
            const float* gxr = gxp + ((size_t)tn * BB + b0) * G4 + gr;
#pragma unroll
            for (int b = 0; b < 8; b++) gxn[b] = __ldg(gxr + (size_t)b * G4);
        }
        __syncthreads();   // h2 stores happen-before the release publish
        if (tid == 0) rel_store(&d_flag[grp][slice], s + 1);
        // history write AFTER publish — consumed only by later kernels
        if (tid < 256) {
            int k = tid >> 3;
            int b = tid & 7;
            hsp[((size_t)t * BB + b0 + b) * HH + ks + k] = hv;
        }
    }
}

// ---------------- emissions: concat(hs_f, hs_b) @ cls_w^T + cls_b ----------------
__global__ void __launch_bounds__(256) k_emis(const float* __restrict__ clsw,
                                              const float* __restrict__ clsb) {
    __shared__ float cw[TT * 512];
    __shared__ float cb[32];
    int tid = threadIdx.x;
    for (int i = tid; i < TT * 512; i += 256) cw[i] = clsw[i];
    if (tid < TT) cb[tid] = clsb[tid];
    __syncthreads();

    int warp = tid >> 5, lane = tid & 31;
    int w = blockIdx.x * 8 + warp;
    int b = w >> 9, s = w & 511;
    const float* hf = d_hs[0] + ((size_t)s * BB + b) * HH;
    const float* hb = d_hs[1] + ((size_t)s * BB + b) * HH;
    float hv[16];
#pragma unroll
    for (int i = 0; i < 8; i++) {
        hv[i] = hf[lane + 32 * i];
        hv[8 + i] = hb[lane + 32 * i];
    }
#pragma unroll 1
    for (int o = 0; o < TT; o++) {
        const float* c0 = cw + o * 512;
        float sum = 0.f;
#pragma unroll
        for (int i = 0; i < 8; i++) {
            sum = fmaf(hv[i], c0[lane + 32 * i], sum);
            sum = fmaf(hv[8 + i], c0[256 + lane + 32 * i], sum);
        }
#pragma unroll
        for (int off = 16; off > 0; off >>= 1)
            sum += __shfl_down_sync(0xffffffffu, sum, off);
        if (lane == 0) d_emis[(size_t)w * TT + o] = sum + cb[o];
    }
}

// ---------------- CRF: blocks 0..63 = loss forward, 64..127 = Viterbi decode -------
__global__ void __launch_bounds__(32) k_crf(const int* __restrict__ labels,
                                            const int* __restrict__ mask,
                                            const float* __restrict__ startt,
                                            const float* __restrict__ endt,
                                            const float* __restrict__ trans,
                                            float* __restrict__ tok_out) {
    int which = blockIdx.x >> 6;
    int b = blockIdx.x & 63;
    int ln = threadIdx.x;
    __shared__ float tr[TT * TT];
    __shared__ float al[TT];
    __shared__ unsigned char bp[SS - 1][TT];
    for (int i = ln; i < TT * TT; i += 32) tr[i] = trans[i];
    __syncwarp();

    if (which == 0) {
        // ---- loss ----
        float part = 0.f;
        for (int s = ln; s < SS; s += 32) {
            int tg = labels[(size_t)b * SS + s];
            float mf = (float)mask[(size_t)b * SS + s];
            part += d_emis[((size_t)b * SS + s) * TT + tg] * mf;
            if (s >= 1) {
                int tp = labels[(size_t)b * SS + s - 1];
                part += tr[tp * TT + tg] * mf;
            }
        }
#pragma unroll
        for (int off = 16; off > 0; off >>= 1)
            part += __shfl_down_sync(0xffffffffu, part, off);
        float num = 0.f;
        if (ln == 0) {
            num = part + startt[labels[(size_t)b * SS]];
            int cnt = 0;
            for (int s = 0; s < SS; s++) cnt += mask[(size_t)b * SS + s];
            num += endt[labels[(size_t)b * SS + cnt - 1]];
        }

        if (ln < TT) al[ln] = startt[ln] + d_emis[((size_t)b * SS) * TT + ln];
        __syncwarp();
        for (int s = 1; s < SS; s++) {
            int m = mask[(size_t)b * SS + s];
            float nv = 0.f;
            if (ln < TT) {
                float v[TT];
                float mx = -1e30f;
#pragma unroll
                for (int i = 0; i < TT; i++) {
                    v[i] = al[i] + tr[i * TT + ln];
                    mx = fmaxf(mx, v[i]);
                }
                float sum = 0.f;
#pragma unroll
                for (int i = 0; i < TT; i++) sum += expf(v[i] - mx);
                nv = mx + logf(sum) + d_emis[((size_t)b * SS + s) * TT + ln];
            }
            __syncwarp();
            if (ln < TT && m > 0) al[ln] = nv;
            __syncwarp();
        }
        if (ln == 0) {
            float mx = -1e30f;
            for (int j = 0; j < TT; j++) mx = fmaxf(mx, al[j] + endt[j]);
            float sum = 0.f;
            for (int j = 0; j < TT; j++) sum += expf(al[j] + endt[j] - mx);
            d_nd[b] = num - (mx + logf(sum));
        }
    } else {
        // ---- Viterbi decode ----
        if (ln < TT) al[ln] = startt[ln] + d_emis[((size_t)b * SS) * TT + ln];
        __syncwarp();
        for (int s = 1; s < SS; s++) {
            int m = mask[(size_t)b * SS + s];
            float nv = 0.f;
            int arg = 0;
            if (ln < TT) {
                float mx = -1e30f;
#pragma unroll
                for (int i = 0; i < TT; i++) {
                    float v = al[i] + tr[i * TT + ln];
                    if (v > mx) { mx = v; arg = i; }
                }
                nv = mx + d_emis[((size_t)b * SS + s) * TT + ln];
            }
            __syncwarp();
            if (ln < TT) {
                if (m > 0) { al[ln] = nv; bp[s - 1][ln] = (unsigned char)arg; }
                else bp[s - 1][ln] = (unsigned char)ln;
            }
            __syncwarp();
        }
        if (ln == 0) {
            float mx = -1e30f;
            int lt = 0;
            for (int j = 0; j < TT; j++) {
                float v = al[j] + endt[j];
                if (v > mx) { mx = v; lt = j; }
            }
            tok_out[(size_t)b * SS + (SS - 1)] = (float)lt;
            int tg = lt;
            for (int s = SS - 2; s >= 0; s--) {
                tg = bp[s][tg];
                tok_out[(size_t)b * SS + s] = (float)tg;
            }
        }
    }
}

// ---------------- final loss reduce ----------------
__global__ void __launch_bounds__(64) k_final(float* __restrict__ out) {
    int tid = threadIdx.x;
    float v = d_nd[tid];
#pragma unroll
    for (int off = 16; off > 0; off >>= 1) v += __shfl_down_sync(0xffffffffu, v, off);
    __shared__ float w[2];
    if ((tid & 31) == 0) w[tid >> 5] = v;
    __syncthreads();
    if (tid == 0) out[0] = -(w[0] + w[1]) / (float)BB;
}

// ---------------- launch ----------------
extern "C" void kernel_launch(void* const* d_in, const int* in_sizes, int n_in,
                              void* d_out, int out_size) {
    const int* tok     = (const int*)d_in[0];
    const int* ctok    = (const int*)d_in[1];
    const int* labels  = (const int*)d_in[2];
    const int* amask   = (const int*)d_in[3];
    const float* wemb  = (const float*)d_in[4];
    const float* cemb  = (const float*)d_in[5];
    const float* convw = (const float*)d_in[6];
    const float* convb = (const float*)d_in[7];
    const float* wihf  = (const float*)d_in[8];
    const float* whhf  = (const float*)d_in[9];
    const float* bf    = (const float*)d_in[10];
    const float* wihb  = (const float*)d_in[11];
    const float* whhb  = (const float*)d_in[12];
    const float* bb    = (const float*)d_in[13];
    const float* clsw  = (const float*)d_in[14];
    const float* clsb  = (const float*)d_in[15];
    const float* startt = (const float*)d_in[16];
    const float* endt   = (const float*)d_in[17];
    const float* trans  = (const float*)d_in[18];
    float* out = (float*)d_out;
    int tok_off = out_size - BB * SS;
    if (tok_off < 0) tok_off = 0;

    k_init<<<1, 128>>>();
    k_embed<<<BS, 128>>>(tok, ctok, wemb, cemb, convw, convb);
    dim3 gg(BS / 128, G4 / 64, 2);
    k_gemm_gx<<<gg, 256>>>(wihf, bf, wihb, bb);
    k_lstm<<<128, 512>>>(whhf, whhb);
    k_emis<<<BS / 8, 256>>>(clsw, clsb);
    k_crf<<<2 * BB, 32>>>(labels, amask, startt, endt, trans, out + tok_off);
    k_final<<<1, 64>>>(out);
}

// round 12
// speedup vs baseline: 1.7348x; 1.3824x over previous
#include <cuda_runtime.h>
#include <math.h>
#include <stdint.h>

#define BB 64
#define SS 512
#define BS (BB*SS)
#define LL 16
#define WD 200
#define CD 30
#define FN 4
#define CF 120
#define KW 3
#define DD 320
#define HH 256
#define G4 1024
#define TT 17
#define LC 14

// ---------------- static scratch (no allocs allowed) ----------------
__device__ float d_z[BS * DD];                    // [B*S, 320]
__device__ float d_gx[2][(size_t)SS * BB * G4];   // [dir][S,B,1024]
__device__ float d_hs[2][(size_t)SS * BB * HH];   // [dir][S,B,256]
__device__ float d_h2[16][2][HH * 8];             // [grp][parity][k*8+b] h exchange
__device__ float d_emis[(size_t)BS * TT];         // [B,S,17]
__device__ float d_nd[BB];
__device__ int   d_ctr[16];

__device__ __forceinline__ float sigf(float x) { return 1.0f / (1.0f + expf(-x)); }

__device__ __forceinline__ int acq_load(const int* p) {
    int v;
    asm volatile("ld.global.acquire.gpu.b32 %0,[%1];" : "=r"(v) : "l"(p) : "memory");
    return v;
}

// ---- packed f32x2 helpers (sm_103a FFMA2) ----
__device__ __forceinline__ unsigned long long fdup(float w) {
    unsigned long long d;
    asm("mov.b64 %0, {%1, %1};" : "=l"(d) : "f"(w));
    return d;
}
__device__ __forceinline__ void ffma2(unsigned long long& a, unsigned long long x,
                                      unsigned long long y) {
    asm("fma.rn.f32x2 %0, %1, %2, %0;" : "+l"(a) : "l"(x), "l"(y));
}
__device__ __forceinline__ unsigned long long addx2(unsigned long long a,
                                                    unsigned long long b) {
    unsigned long long r;
    asm("add.rn.f32x2 %0, %1, %2;" : "=l"(r) : "l"(a), "l"(b));
    return r;
}
__device__ __forceinline__ float2 unpk(unsigned long long a) {
    float2 f;
    asm("mov.b64 {%0, %1}, %2;" : "=f"(f.x), "=f"(f.y) : "l"(a));
    return f;
}

// ---------------- init (reset barrier counters each launch) ----------------
__global__ void k_init() {
    int t = threadIdx.x;
    if (t < 16) d_ctr[t] = 0;
}

// ---------------- embeddings + char CNN + concat ----------------
__global__ void __launch_bounds__(128) k_embed(const int* __restrict__ tok,
                                               const int* __restrict__ ctok,
                                               const float* __restrict__ wemb,
                                               const float* __restrict__ cemb,
                                               const float* __restrict__ convw,
                                               const float* __restrict__ convb) {
    int w = blockIdx.x;  // word = b*S + s
    __shared__ float ce[LL][CD];
    __shared__ int cid[LL];
    int tid = threadIdx.x;
    if (tid < LL) cid[tid] = ctok[(size_t)w * LL + tid];
    __syncthreads();
    for (int i = tid; i < LL * CD; i += 128) {
        int l = i / CD, c = i % CD;
        ce[l][c] = cemb[cid[l] * CD + c];
    }
    __syncthreads();
    if (tid < CF) {
        int o = tid, ic = o >> 2;
        float w0 = convw[o * 3 + 0], w1 = convw[o * 3 + 1], w2 = convw[o * 3 + 2];
        float m = -1e30f;
#pragma unroll
        for (int t = 0; t < LC; t++) {
            float v = ce[t][ic] * w0 + ce[t + 1][ic] * w1 + ce[t + 2][ic] * w2;
            m = fmaxf(m, v);
        }
        d_z[(size_t)w * DD + WD + o] = m + convb[o];
    }
    const float* wr = wemb + (size_t)tok[w] * WD;
    for (int j = tid; j < WD; j += 128) d_z[(size_t)w * DD + j] = wr[j];
}

// ---------------- input-side GEMM with FFMA2: z[BS,320] @ W^T -> gx ----------------
__global__ void __launch_bounds__(256, 2) k_gemm_gx(const float* __restrict__ Wf,
                                                    const float* __restrict__ biasf,
                                                    const float* __restrict__ Wb,
                                                    const float* __restrict__ biasb) {
    int dir = blockIdx.z;
    const float* __restrict__ Wm = dir ? Wb : Wf;
    const float* __restrict__ bias = dir ? biasb : biasf;
    float* out = d_gx[dir];
    const float* __restrict__ Z = d_z;

    int mBase = blockIdx.x * 128;
    int nBase = blockIdx.y * 64;

    __shared__ float As[16][132];
    __shared__ float Bs[16][68];

    int tid = threadIdx.x;
    int ty = tid >> 4;
    int tx = tid & 15;

    unsigned long long acc2[8][2];
#pragma unroll
    for (int i = 0; i < 8; i++) { acc2[i][0] = 0ull; acc2[i][1] = 0ull; }

    for (int k0 = 0; k0 < DD; k0 += 16) {
#pragma unroll
        for (int r = 0; r < 2; r++) {
            int idx = tid + r * 256;
            int row = idx >> 2, kq = idx & 3;
            float4 v = *(const float4*)&Z[(size_t)(mBase + row) * DD + k0 + kq * 4];
            As[kq * 4 + 0][row] = v.x;
            As[kq * 4 + 1][row] = v.y;
            As[kq * 4 + 2][row] = v.z;
            As[kq * 4 + 3][row] = v.w;
        }
        {
            int row = tid >> 2, kq = tid & 3;
            float4 v = *(const float4*)&Wm[(size_t)(nBase + row) * DD + k0 + kq * 4];
            Bs[kq * 4 + 0][row] = v.x;
            Bs[kq * 4 + 1][row] = v.y;
            Bs[kq * 4 + 2][row] = v.z;
            Bs[kq * 4 + 3][row] = v.w;
        }
        __syncthreads();
#pragma unroll
        for (int kk = 0; kk < 16; kk++) {
            float4 a0 = *(const float4*)&As[kk][ty * 8];
            float4 a1 = *(const float4*)&As[kk][ty * 8 + 4];
            ulonglong2 bq = *(const ulonglong2*)&Bs[kk][tx * 4];
            float av[8] = {a0.x, a0.y, a0.z, a0.w, a1.x, a1.y, a1.z, a1.w};
#pragma unroll
            for (int i = 0; i < 8; i++) {
                unsigned long long ad = fdup(av[i]);
                ffma2(acc2[i][0], bq.x, ad);
                ffma2(acc2[i][1], bq.y, ad);
            }
        }
        __syncthreads();
    }

    float bq0 = bias[nBase + tx * 4 + 0], bq1 = bias[nBase + tx * 4 + 1];
    float bq2 = bias[nBase + tx * 4 + 2], bq3 = bias[nBase + tx * 4 + 3];
#pragma unroll
    for (int i = 0; i < 8; i++) {
        int m = mBase + ty * 8 + i;
        int b = m >> 9, s = m & 511;
        size_t ro = ((size_t)s * BB + b) * (size_t)G4 + nBase + tx * 4;
        float2 p0 = unpk(acc2[i][0]);
        float2 p1 = unpk(acc2[i][1]);
        float4 o4;
        o4.x = p0.x + bq0;
        o4.y = p0.y + bq1;
        o4.z = p1.x + bq2;
        o4.w = p1.y + bq3;
        *(float4*)&out[ro] = o4;
    }
}

// ---------------- BiLSTM: R6 structure (best verified), one surgical change -------
// 128 CTAs (16 groups x 8 slices) x 512 thr; W in regs; h exchange via L2 stcg/ldcg;
// fence + atomicAdd counter + tid0 acquire spin (proven fastest sync).
// ONLY change vs R6: the scattered d_hs history store moved AFTER the publish, so
// the gpu-scope fence drains only the compact 1KB h2 stores (shorter crit path).
__global__ void __launch_bounds__(512, 1)
k_lstm(const float* __restrict__ whf, const float* __restrict__ whb) {
    __shared__ float h_sm[2 * HH * 8];   // [parity][256 k][8 batch]
    __shared__ float g_sm[128 * 8];      // [local gate row][8 batch]
    __shared__ float c_sm[32 * 8];       // [k*8+b]

    int blk = blockIdx.x;
    int slice = blk & 7;
    int grp = blk >> 3;          // 0..15
    int dir = grp >> 3;
    int bg = grp & 7;
    const float* Wd = dir ? whb : whf;
    int tid = threadIdx.x;
    int row = tid >> 2;          // 0..127 local gate row
    int sub = tid & 3;           // k-interleave lane
    int gt = row >> 5;           // gate 0..3
    int kl = row & 31;
    int ks = slice * 32;
    int gr = gt * 256 + ks + kl; // gate row in [0,1024)
    const float* gxp = d_gx[dir];
    float* hsp = d_hs[dir];
    int b0 = bg * 8;

    // W into registers: w_reg[kk] = W[gr][4*kk + sub]
    float w_reg[64];
    {
        const float* wr = Wd + (size_t)gr * HH + sub;
#pragma unroll
        for (int kk = 0; kk < 64; kk++) w_reg[kk] = __ldg(wr + 4 * kk);
    }
    if (tid < 256) c_sm[tid] = 0.f;
    __syncthreads();

    // preload gx for step 0 (sub==0 threads hold gxn for their row)
    float gxn[8];
    if (sub == 0) {
        int t0 = dir ? (SS - 1) : 0;
        const float* gxr = gxp + ((size_t)t0 * BB + b0) * G4 + gr;
#pragma unroll
        for (int b = 0; b < 8; b++) gxn[b] = __ldg(gxr + (size_t)b * G4);
    }

    for (int s = 0; s < SS; s++) {
        int t = dir ? (SS - 1 - s) : s;
        unsigned long long a0 = 0ull, a1 = 0ull, a2 = 0ull, a3 = 0ull;

        if (s > 0) {
            int parp = (s & 1) ^ 1;   // parity of step s-1
            // wait for all 8 CTAs of the group to finish step s-1
            if (tid == 0) {
                int tgt = 8 * s;
                while (acq_load(&d_ctr[grp]) < tgt) {}
            }
            __syncthreads();
            // load h(s-1) from L2 into smem (coalesced, layout already [k*8+b])
            {
                const float4* src = (const float4*)(d_h2[grp][parp]);
                float4 v = __ldcg(src + tid);
                *(float4*)&h_sm[parp * (HH * 8) + tid * 4] = v;
            }
            __syncthreads();

            const float* hb = h_sm + parp * (HH * 8) + sub * 8;
#pragma unroll
            for (int kk = 0; kk < 64; kk++) {
                unsigned long long wd = fdup(w_reg[kk]);
                const ulonglong2* hp = (const ulonglong2*)(hb + kk * 32);
                ulonglong2 q0 = hp[0];   // batches 0,1 | 2,3
                ulonglong2 q1 = hp[1];   // batches 4,5 | 6,7
                ffma2(a0, q0.x, wd);
                ffma2(a1, q0.y, wd);
                ffma2(a2, q1.x, wd);
                ffma2(a3, q1.y, wd);
            }
            // reduce across the 4 sub lanes (adjacent in warp)
            a0 = addx2(a0, __shfl_xor_sync(0xffffffffu, a0, 1));
            a1 = addx2(a1, __shfl_xor_sync(0xffffffffu, a1, 1));
            a2 = addx2(a2, __shfl_xor_sync(0xffffffffu, a2, 1));
            a3 = addx2(a3, __shfl_xor_sync(0xffffffffu, a3, 1));
            a0 = addx2(a0, __shfl_xor_sync(0xffffffffu, a0, 2));
            a1 = addx2(a1, __shfl_xor_sync(0xffffffffu, a1, 2));
            a2 = addx2(a2, __shfl_xor_sync(0xffffffffu, a2, 2));
            a3 = addx2(a3, __shfl_xor_sync(0xffffffffu, a3, 2));
        }
        if (sub == 0) {
            float2 p0 = unpk(a0), p1 = unpk(a1), p2 = unpk(a2), p3 = unpk(a3);
            float4 v0, v1;
            v0.x = p0.x + gxn[0]; v0.y = p0.y + gxn[1];
            v0.z = p1.x + gxn[2]; v0.w = p1.y + gxn[3];
            v1.x = p2.x + gxn[4]; v1.y = p2.y + gxn[5];
            v1.z = p3.x + gxn[6]; v1.w = p3.y + gxn[7];
            *(float4*)&g_sm[row * 8] = v0;
            *(float4*)&g_sm[row * 8 + 4] = v1;
        }
        __syncthreads();

        // elementwise LSTM cell: task tid<256, k = tid>>3, b = tid&7 (coalesced h2 write)
        int par = s & 1;
        float hv = 0.f;
        if (tid < 256) {
            int k = tid >> 3;
            int b = tid & 7;
            float gi = g_sm[(0 * 32 + k) * 8 + b];
            float gf = g_sm[(1 * 32 + k) * 8 + b];
            float gg = g_sm[(2 * 32 + k) * 8 + b];
            float go = g_sm[(3 * 32 + k) * 8 + b];
            float c = c_sm[k * 8 + b];
            float cn = sigf(gf) * c + sigf(gi) * tanhf(gg);
            hv = sigf(go) * tanhf(cn);
            c_sm[k * 8 + b] = cn;
            __stcg(&d_h2[grp][par][(ks + k) * 8 + b], hv);
        }
        // prefetch next step's gx (independent of the barrier)
        if (sub == 0 && s + 1 < SS) {
            int tn = dir ? (SS - 2 - s) : (s + 1);
            const float* gxr = gxp + ((size_t)tn * BB + b0) * G4 + gr;
#pragma unroll
            for (int b = 0; b < 8; b++) gxn[b] = __ldg(gxr + (size_t)b * G4);
        }
        if (tid < 256) __threadfence();   // drains only the compact h2 stores now
        __syncthreads();
        if (tid == 0) atomicAdd(&d_ctr[grp], 1);
        // history write AFTER publish — consumed only by later kernels
        if (tid < 256) {
            int k = tid >> 3;
            int b = tid & 7;
            hsp[((size_t)t * BB + b0 + b) * HH + ks + k] = hv;
        }
    }
}

// ---------------- emissions: concat(hs_f, hs_b) @ cls_w^T + cls_b ----------------
__global__ void __launch_bounds__(256) k_emis(const float* __restrict__ clsw,
                                              const float* __restrict__ clsb) {
    __shared__ float cw[TT * 512];
    __shared__ float cb[32];
    int tid = threadIdx.x;
    for (int i = tid; i < TT * 512; i += 256) cw[i] = clsw[i];
    if (tid < TT) cb[tid] = clsb[tid];
    __syncthreads();

    int warp = tid >> 5, lane = tid & 31;
    int w = blockIdx.x * 8 + warp;
    int b = w >> 9, s = w & 511;
    const float* hf = d_hs[0] + ((size_t)s * BB + b) * HH;
    const float* hb = d_hs[1] + ((size_t)s * BB + b) * HH;
    float hv[16];
#pragma unroll
    for (int i = 0; i < 8; i++) {
        hv[i] = hf[lane + 32 * i];
        hv[8 + i] = hb[lane + 32 * i];
    }
#pragma unroll 1
    for (int o = 0; o < TT; o++) {
        const float* c0 = cw + o * 512;
        float sum = 0.f;
#pragma unroll
        for (int i = 0; i < 8; i++) {
            sum = fmaf(hv[i], c0[lane + 32 * i], sum);
            sum = fmaf(hv[8 + i], c0[256 + lane + 32 * i], sum);
        }
#pragma unroll
        for (int off = 16; off > 0; off >>= 1)
            sum += __shfl_down_sync(0xffffffffu, sum, off);
        if (lane == 0) d_emis[(size_t)w * TT + o] = sum + cb[o];
    }
}

// ---------------- CRF: blocks 0..63 = loss forward, 64..127 = Viterbi decode -------
__global__ void __launch_bounds__(32) k_crf(const int* __restrict__ labels,
                                            const int* __restrict__ mask,
                                            const float* __restrict__ startt,
                                            const float* __restrict__ endt,
                                            const float* __restrict__ trans,
                                            float* __restrict__ tok_out) {
    int which = blockIdx.x >> 6;
    int b = blockIdx.x & 63;
    int ln = threadIdx.x;
    __shared__ float tr[TT * TT];
    __shared__ float al[TT];
    __shared__ unsigned char bp[SS - 1][TT];
    for (int i = ln; i < TT * TT; i += 32) tr[i] = trans[i];
    __syncwarp();

    if (which == 0) {
        // ---- loss ----
        float part = 0.f;
        for (int s = ln; s < SS; s += 32) {
            int tg = labels[(size_t)b * SS + s];
            float mf = (float)mask[(size_t)b * SS + s];
            part += d_emis[((size_t)b * SS + s) * TT + tg] * mf;
            if (s >= 1) {
                int tp = labels[(size_t)b * SS + s - 1];
                part += tr[tp * TT + tg] * mf;
            }
        }
#pragma unroll
        for (int off = 16; off > 0; off >>= 1)
            part += __shfl_down_sync(0xffffffffu, part, off);
        float num = 0.f;
        if (ln == 0) {
            num = part + startt[labels[(size_t)b * SS]];
            int cnt = 0;
            for (int s = 0; s < SS; s++) cnt += mask[(size_t)b * SS + s];
            num += endt[labels[(size_t)b * SS + cnt - 1]];
        }

        if (ln < TT) al[ln] = startt[ln] + d_emis[((size_t)b * SS) * TT + ln];
        __syncwarp();
        for (int s = 1; s < SS; s++) {
            int m = mask[(size_t)b * SS + s];
            float nv = 0.f;
            if (ln < TT) {
                float v[TT];
                float mx = -1e30f;
#pragma unroll
                for (int i = 0; i < TT; i++) {
                    v[i] = al[i] + tr[i * TT + ln];
                    mx = fmaxf(mx, v[i]);
                }
                float sum = 0.f;
#pragma unroll
                for (int i = 0; i < TT; i++) sum += expf(v[i] - mx);
                nv = mx + logf(sum) + d_emis[((size_t)b * SS + s) * TT + ln];
            }
            __syncwarp();
            if (ln < TT && m > 0) al[ln] = nv;
            __syncwarp();
        }
        if (ln == 0) {
            float mx = -1e30f;
            for (int j = 0; j < TT; j++) mx = fmaxf(mx, al[j] + endt[j]);
            float sum = 0.f;
            for (int j = 0; j < TT; j++) sum += expf(al[j] + endt[j] - mx);
            d_nd[b] = num - (mx + logf(sum));
        }
    } else {
        // ---- Viterbi decode ----
        if (ln < TT) al[ln] = startt[ln] + d_emis[((size_t)b * SS) * TT + ln];
        __syncwarp();
        for (int s = 1; s < SS; s++) {
            int m = mask[(size_t)b * SS + s];
            float nv = 0.f;
            int arg = 0;
            if (ln < TT) {
                float mx = -1e30f;
#pragma unroll
                for (int i = 0; i < TT; i++) {
                    float v = al[i] + tr[i * TT + ln];
                    if (v > mx) { mx = v; arg = i; }
                }
                nv = mx + d_emis[((size_t)b * SS + s) * TT + ln];
            }
            __syncwarp();
            if (ln < TT) {
                if (m > 0) { al[ln] = nv; bp[s - 1][ln] = (unsigned char)arg; }
                else bp[s - 1][ln] = (unsigned char)ln;
            }
            __syncwarp();
        }
        if (ln == 0) {
            float mx = -1e30f;
            int lt = 0;
            for (int j = 0; j < TT; j++) {
                float v = al[j] + endt[j];
                if (v > mx) { mx = v; lt = j; }
            }
            tok_out[(size_t)b * SS + (SS - 1)] = (float)lt;
            int tg = lt;
            for (int s = SS - 2; s >= 0; s--) {
                tg = bp[s][tg];
                tok_out[(size_t)b * SS + s] = (float)tg;
            }
        }
    }
}

// ---------------- final loss reduce ----------------
__global__ void __launch_bounds__(64) k_final(float* __restrict__ out) {
    int tid = threadIdx.x;
    float v = d_nd[tid];
#pragma unroll
    for (int off = 16; off > 0; off >>= 1) v += __shfl_down_sync(0xffffffffu, v, off);
    __shared__ float w[2];
    if ((tid & 31) == 0) w[tid >> 5] = v;
    __syncthreads();
    if (tid == 0) out[0] = -(w[0] + w[1]) / (float)BB;
}

// ---------------- launch ----------------
extern "C" void kernel_launch(void* const* d_in, const int* in_sizes, int n_in,
                              void* d_out, int out_size) {
    const int* tok     = (const int*)d_in[0];
    const int* ctok    = (const int*)d_in[1];
    const int* labels  = (const int*)d_in[2];
    const int* amask   = (const int*)d_in[3];
    const float* wemb  = (const float*)d_in[4];
    const float* cemb  = (const float*)d_in[5];
    const float* convw = (const float*)d_in[6];
    const float* convb = (const float*)d_in[7];
    const float* wihf  = (const float*)d_in[8];
    const float* whhf  = (const float*)d_in[9];
    const float* bf    = (const float*)d_in[10];
    const float* wihb  = (const float*)d_in[11];
    const float* whhb  = (const float*)d_in[12];
    const float* bb    = (const float*)d_in[13];
    const float* clsw  = (const float*)d_in[14];
    const float* clsb  = (const float*)d_in[15];
    const float* startt = (const float*)d_in[16];
    const float* endt   = (const float*)d_in[17];
    const float* trans  = (const float*)d_in[18];
    float* out = (float*)d_out;
    int tok_off = out_size - BB * SS;
    if (tok_off < 0) tok_off = 0;

    k_init<<<1, 32>>>();
    k_embed<<<BS, 128>>>(tok, ctok, wemb, cemb, convw, convb);
    dim3 gg(BS / 128, G4 / 64, 2);
    k_gemm_gx<<<gg, 256>>>(wihf, bf, wihb, bb);
    k_lstm<<<128, 512>>>(whhf, whhb);
    k_emis<<<BS / 8, 256>>>(clsw, clsb);
    k_crf<<<2 * BB, 32>>>(labels, amask, startt, endt, trans, out + tok_off);
    k_final<<<1, 64>>>(out);
}

// round 13
// speedup vs baseline: 1.7861x; 1.0296x over previous
#include <cuda_runtime.h>
#include <math.h>
#include <stdint.h>

#define BB 64
#define SS 512
#define BS (BB*SS)
#define LL 16
#define WD 200
#define CD 30
#define FN 4
#define CF 120
#define KW 3
#define DD 320
#define HH 256
#define G4 1024
#define TT 17
#define LC 14

// ---------------- static scratch (no allocs allowed) ----------------
__device__ float d_z[BS * DD];                    // [B*S, 320]
__device__ float d_gx[2][(size_t)SS * BB * G4];   // [dir][S,B,1024]
__device__ float d_hs[2][(size_t)SS * BB * HH];   // [dir][S,B,256]
__device__ float d_h2[16][2][HH * 8];             // [grp][parity][k*8+b] h exchange
__device__ float d_emis[(size_t)BS * TT];         // [B,S,17]
__device__ float d_nd[BB];
__device__ int   d_ctr[16];

__device__ __forceinline__ float sigf(float x) { return 1.0f / (1.0f + expf(-x)); }

__device__ __forceinline__ int acq_load(const int* p) {
    int v;
    asm volatile("ld.global.acquire.gpu.b32 %0,[%1];" : "=r"(v) : "l"(p) : "memory");
    return v;
}

// ---- packed f32x2 helpers (sm_103a FFMA2) ----
__device__ __forceinline__ unsigned long long fdup(float w) {
    unsigned long long d;
    asm("mov.b64 %0, {%1, %1};" : "=l"(d) : "f"(w));
    return d;
}
__device__ __forceinline__ void ffma2(unsigned long long& a, unsigned long long x,
                                      unsigned long long y) {
    asm("fma.rn.f32x2 %0, %1, %2, %0;" : "+l"(a) : "l"(x), "l"(y));
}
__device__ __forceinline__ unsigned long long addx2(unsigned long long a,
                                                    unsigned long long b) {
    unsigned long long r;
    asm("add.rn.f32x2 %0, %1, %2;" : "=l"(r) : "l"(a), "l"(b));
    return r;
}
__device__ __forceinline__ float2 unpk(unsigned long long a) {
    float2 f;
    asm("mov.b64 {%0, %1}, %2;" : "=f"(f.x), "=f"(f.y) : "l"(a));
    return f;
}

// ---------------- init (reset barrier counters each launch) ----------------
__global__ void k_init() {
    int t = threadIdx.x;
    if (t < 16) d_ctr[t] = 0;
}

// ---------------- embeddings + char CNN + concat ----------------
__global__ void __launch_bounds__(128) k_embed(const int* __restrict__ tok,
                                               const int* __restrict__ ctok,
                                               const float* __restrict__ wemb,
                                               const float* __restrict__ cemb,
                                               const float* __restrict__ convw,
                                               const float* __restrict__ convb) {
    int w = blockIdx.x;  // word = b*S + s
    __shared__ float ce[LL][CD];
    __shared__ int cid[LL];
    int tid = threadIdx.x;
    if (tid < LL) cid[tid] = ctok[(size_t)w * LL + tid];
    __syncthreads();
    for (int i = tid; i < LL * CD; i += 128) {
        int l = i / CD, c = i % CD;
        ce[l][c] = cemb[cid[l] * CD + c];
    }
    __syncthreads();
    if (tid < CF) {
        int o = tid, ic = o >> 2;
        float w0 = convw[o * 3 + 0], w1 = convw[o * 3 + 1], w2 = convw[o * 3 + 2];
        float m = -1e30f;
#pragma unroll
        for (int t = 0; t < LC; t++) {
            float v = ce[t][ic] * w0 + ce[t + 1][ic] * w1 + ce[t + 2][ic] * w2;
            m = fmaxf(m, v);
        }
        d_z[(size_t)w * DD + WD + o] = m + convb[o];
    }
    const float* wr = wemb + (size_t)tok[w] * WD;
    for (int j = tid; j < WD; j += 128) d_z[(size_t)w * DD + j] = wr[j];
}

// ---------------- input-side GEMM with FFMA2: z[BS,320] @ W^T -> gx ----------------
__global__ void __launch_bounds__(256, 2) k_gemm_gx(const float* __restrict__ Wf,
                                                    const float* __restrict__ biasf,
                                                    const float* __restrict__ Wb,
                                                    const float* __restrict__ biasb) {
    int dir = blockIdx.z;
    const float* __restrict__ Wm = dir ? Wb : Wf;
    const float* __restrict__ bias = dir ? biasb : biasf;
    float* out = d_gx[dir];
    const float* __restrict__ Z = d_z;

    int mBase = blockIdx.x * 128;
    int nBase = blockIdx.y * 64;

    __shared__ float As[16][132];
    __shared__ float Bs[16][68];

    int tid = threadIdx.x;
    int ty = tid >> 4;
    int tx = tid & 15;

    unsigned long long acc2[8][2];
#pragma unroll
    for (int i = 0; i < 8; i++) { acc2[i][0] = 0ull; acc2[i][1] = 0ull; }

    for (int k0 = 0; k0 < DD; k0 += 16) {
#pragma unroll
        for (int r = 0; r < 2; r++) {
            int idx = tid + r * 256;
            int row = idx >> 2, kq = idx & 3;
            float4 v = *(const float4*)&Z[(size_t)(mBase + row) * DD + k0 + kq * 4];
            As[kq * 4 + 0][row] = v.x;
            As[kq * 4 + 1][row] = v.y;
            As[kq * 4 + 2][row] = v.z;
            As[kq * 4 + 3][row] = v.w;
        }
        {
            int row = tid >> 2, kq = tid & 3;
            float4 v = *(const float4*)&Wm[(size_t)(nBase + row) * DD + k0 + kq * 4];
            Bs[kq * 4 + 0][row] = v.x;
            Bs[kq * 4 + 1][row] = v.y;
            Bs[kq * 4 + 2][row] = v.z;
            Bs[kq * 4 + 3][row] = v.w;
        }
        __syncthreads();
#pragma unroll
        for (int kk = 0; kk < 16; kk++) {
            float4 a0 = *(const float4*)&As[kk][ty * 8];
            float4 a1 = *(const float4*)&As[kk][ty * 8 + 4];
            ulonglong2 bq = *(const ulonglong2*)&Bs[kk][tx * 4];
            float av[8] = {a0.x, a0.y, a0.z, a0.w, a1.x, a1.y, a1.z, a1.w};
#pragma unroll
            for (int i = 0; i < 8; i++) {
                unsigned long long ad = fdup(av[i]);
                ffma2(acc2[i][0], bq.x, ad);
                ffma2(acc2[i][1], bq.y, ad);
            }
        }
        __syncthreads();
    }

    float bq0 = bias[nBase + tx * 4 + 0], bq1 = bias[nBase + tx * 4 + 1];
    float bq2 = bias[nBase + tx * 4 + 2], bq3 = bias[nBase + tx * 4 + 3];
#pragma unroll
    for (int i = 0; i < 8; i++) {
        int m = mBase + ty * 8 + i;
        int b = m >> 9, s = m & 511;
        size_t ro = ((size_t)s * BB + b) * (size_t)G4 + nBase + tx * 4;
        float2 p0 = unpk(acc2[i][0]);
        float2 p1 = unpk(acc2[i][1]);
        float4 o4;
        o4.x = p0.x + bq0;
        o4.y = p0.y + bq1;
        o4.z = p1.x + bq2;
        o4.w = p1.y + bq3;
        *(float4*)&out[ro] = o4;
    }
}

// ---------------- BiLSTM: 256 CTAs (16 groups x 16 slices), 256 thr, 2 CTAs/SM ----
// R6 protocol per CTA (W in regs, L2 stcg/ldcg h exchange, fence+atomic+spin), but
// slices halved (16 k each) so TWO independent-group CTAs co-reside per SM: while
// one stalls on its group's sync chain, the other's 8 warps issue compute.
// __launch_bounds__(256,2) caps regs at 128 -> 2 CTAs/SM GUARANTEED (296 slots >=
// 256 CTAs, single wave, spin-safe).
#define NSL 16
#define KSL 16
__global__ void __launch_bounds__(256, 2)
k_lstm(const float* __restrict__ whf, const float* __restrict__ whb) {
    __shared__ float h_sm[2 * HH * 8];   // [parity][256 k][8 batch]
    __shared__ float g_sm[64 * 8];       // [local gate row][8 batch]
    __shared__ float c_sm[KSL * 8];      // [k*8+b]

    int blk = blockIdx.x;
    int slice = blk & (NSL - 1);
    int grp = blk >> 4;          // 0..15
    int dir = grp >> 3;
    int bg = grp & 7;
    const float* Wd = dir ? whb : whf;
    int tid = threadIdx.x;
    int row = tid >> 2;          // 0..63 local gate row
    int sub = tid & 3;           // k-interleave lane
    int gt = row >> 4;           // gate 0..3
    int kl = row & 15;
    int ks = slice * KSL;
    int gr = gt * 256 + ks + kl; // gate row in [0,1024)
    const float* gxp = d_gx[dir];
    float* hsp = d_hs[dir];
    int b0 = bg * 8;

    // W into registers: w_reg[kk] = W[gr][4*kk + sub]
    float w_reg[64];
    {
        const float* wr = Wd + (size_t)gr * HH + sub;
#pragma unroll
        for (int kk = 0; kk < 64; kk++) w_reg[kk] = __ldg(wr + 4 * kk);
    }
    if (tid < KSL * 8) c_sm[tid] = 0.f;
    __syncthreads();

    // preload gx for step 0 (sub==0 threads hold gxn for their row)
    float gxn[8];
    if (sub == 0) {
        int t0 = dir ? (SS - 1) : 0;
        const float* gxr = gxp + ((size_t)t0 * BB + b0) * G4 + gr;
#pragma unroll
        for (int b = 0; b < 8; b++) gxn[b] = __ldg(gxr + (size_t)b * G4);
    }

    for (int s = 0; s < SS; s++) {
        int t = dir ? (SS - 1 - s) : s;
        unsigned long long a0 = 0ull, a1 = 0ull, a2 = 0ull, a3 = 0ull;

        if (s > 0) {
            int parp = (s & 1) ^ 1;   // parity of step s-1
            // wait for all 16 CTAs of the group to finish step s-1
            if (tid == 0) {
                int tgt = NSL * s;
                while (acq_load(&d_ctr[grp]) < tgt) {}
            }
            __syncthreads();
            // load h(s-1) from L2 into smem (512 float4 by 256 threads)
            {
                const float4* src = (const float4*)(d_h2[grp][parp]);
                float* dst = h_sm + parp * (HH * 8);
                float4 v0 = __ldcg(src + tid);
                float4 v1 = __ldcg(src + tid + 256);
                *(float4*)&dst[tid * 4] = v0;
                *(float4*)&dst[(tid + 256) * 4] = v1;
            }
            __syncthreads();

            const float* hb = h_sm + parp * (HH * 8) + sub * 8;
#pragma unroll
            for (int kk = 0; kk < 64; kk++) {
                unsigned long long wd = fdup(w_reg[kk]);
                const ulonglong2* hp = (const ulonglong2*)(hb + kk * 32);
                ulonglong2 q0 = hp[0];   // batches 0,1 | 2,3
                ulonglong2 q1 = hp[1];   // batches 4,5 | 6,7
                ffma2(a0, q0.x, wd);
                ffma2(a1, q0.y, wd);
                ffma2(a2, q1.x, wd);
                ffma2(a3, q1.y, wd);
            }
            // reduce across the 4 sub lanes (adjacent in warp)
            a0 = addx2(a0, __shfl_xor_sync(0xffffffffu, a0, 1));
            a1 = addx2(a1, __shfl_xor_sync(0xffffffffu, a1, 1));
            a2 = addx2(a2, __shfl_xor_sync(0xffffffffu, a2, 1));
            a3 = addx2(a3, __shfl_xor_sync(0xffffffffu, a3, 1));
            a0 = addx2(a0, __shfl_xor_sync(0xffffffffu, a0, 2));
            a1 = addx2(a1, __shfl_xor_sync(0xffffffffu, a1, 2));
            a2 = addx2(a2, __shfl_xor_sync(0xffffffffu, a2, 2));
            a3 = addx2(a3, __shfl_xor_sync(0xffffffffu, a3, 2));
        }
        if (sub == 0) {
            float2 p0 = unpk(a0), p1 = unpk(a1), p2 = unpk(a2), p3 = unpk(a3);
            float4 v0, v1;
            v0.x = p0.x + gxn[0]; v0.y = p0.y + gxn[1];
            v0.z = p1.x + gxn[2]; v0.w = p1.y + gxn[3];
            v1.x = p2.x + gxn[4]; v1.y = p2.y + gxn[5];
            v1.z = p3.x + gxn[6]; v1.w = p3.y + gxn[7];
            *(float4*)&g_sm[row * 8] = v0;
            *(float4*)&g_sm[row * 8 + 4] = v1;
        }
        __syncthreads();

        // elementwise LSTM cell: 128 tasks (k = tid>>3 in [0,16), b = tid&7)
        int par = s & 1;
        float hv = 0.f;
        if (tid < KSL * 8) {
            int k = tid >> 3;
            int b = tid & 7;
            float gi = g_sm[(0 * KSL + k) * 8 + b];
            float gf = g_sm[(1 * KSL + k) * 8 + b];
            float gg = g_sm[(2 * KSL + k) * 8 + b];
            float go = g_sm[(3 * KSL + k) * 8 + b];
            float c = c_sm[tid];
            float cn = sigf(gf) * c + sigf(gi) * tanhf(gg);
            hv = sigf(go) * tanhf(cn);
            c_sm[tid] = cn;
            __stcg(&d_h2[grp][par][(ks + k) * 8 + b], hv);
        }
        // prefetch next step's gx (independent of the barrier)
        if (sub == 0 && s + 1 < SS) {
            int tn = dir ? (SS - 2 - s) : (s + 1);
            const float* gxr = gxp + ((size_t)tn * BB + b0) * G4 + gr;
#pragma unroll
            for (int b = 0; b < 8; b++) gxn[b] = __ldg(gxr + (size_t)b * G4);
        }
        if (tid < KSL * 8) __threadfence();
        __syncthreads();
        if (tid == 0) atomicAdd(&d_ctr[grp], 1);
        // history write AFTER publish — consumed only by later kernels
        if (tid < KSL * 8) {
            int k = tid >> 3;
            int b = tid & 7;
            hsp[((size_t)t * BB + b0 + b) * HH + ks + k] = hv;
        }
    }
}

// ---------------- emissions: concat(hs_f, hs_b) @ cls_w^T + cls_b ----------------
__global__ void __launch_bounds__(256) k_emis(const float* __restrict__ clsw,
                                              const float* __restrict__ clsb) {
    __shared__ float cw[TT * 512];
    __shared__ float cb[32];
    int tid = threadIdx.x;
    for (int i = tid; i < TT * 512; i += 256) cw[i] = clsw[i];
    if (tid < TT) cb[tid] = clsb[tid];
    __syncthreads();

    int warp = tid >> 5, lane = tid & 31;
    int w = blockIdx.x * 8 + warp;
    int b = w >> 9, s = w & 511;
    const float* hf = d_hs[0] + ((size_t)s * BB + b) * HH;
    const float* hb = d_hs[1] + ((size_t)s * BB + b) * HH;
    float hv[16];
#pragma unroll
    for (int i = 0; i < 8; i++) {
        hv[i] = hf[lane + 32 * i];
        hv[8 + i] = hb[lane + 32 * i];
    }
#pragma unroll 1
    for (int o = 0; o < TT; o++) {
        const float* c0 = cw + o * 512;
        float sum = 0.f;
#pragma unroll
        for (int i = 0; i < 8; i++) {
            sum = fmaf(hv[i], c0[lane + 32 * i], sum);
            sum = fmaf(hv[8 + i], c0[256 + lane + 32 * i], sum);
        }
#pragma unroll
        for (int off = 16; off > 0; off >>= 1)
            sum += __shfl_down_sync(0xffffffffu, sum, off);
        if (lane == 0) d_emis[(size_t)w * TT + o] = sum + cb[o];
    }
}

// ---------------- CRF: blocks 0..63 = loss forward, 64..127 = Viterbi decode -------
__global__ void __launch_bounds__(32) k_crf(const int* __restrict__ labels,
                                            const int* __restrict__ mask,
                                            const float* __restrict__ startt,
                                            const float* __restrict__ endt,
                                            const float* __restrict__ trans,
                                            float* __restrict__ tok_out) {
    int which = blockIdx.x >> 6;
    int b = blockIdx.x & 63;
    int ln = threadIdx.x;
    __shared__ float tr[TT * TT];
    __shared__ float al[TT];
    __shared__ unsigned char bp[SS - 1][TT];
    for (int i = ln; i < TT * TT; i += 32) tr[i] = trans[i];
    __syncwarp();

    if (which == 0) {
        // ---- loss ----
        float part = 0.f;
        for (int s = ln; s < SS; s += 32) {
            int tg = labels[(size_t)b * SS + s];
            float mf = (float)mask[(size_t)b * SS + s];
            part += d_emis[((size_t)b * SS + s) * TT + tg] * mf;
            if (s >= 1) {
                int tp = labels[(size_t)b * SS + s - 1];
                part += tr[tp * TT + tg] * mf;
            }
        }
#pragma unroll
        for (int off = 16; off > 0; off >>= 1)
            part += __shfl_down_sync(0xffffffffu, part, off);
        float num = 0.f;
        if (ln == 0) {
            num = part + startt[labels[(size_t)b * SS]];
            int cnt = 0;
            for (int s = 0; s < SS; s++) cnt += mask[(size_t)b * SS + s];
            num += endt[labels[(size_t)b * SS + cnt - 1]];
        }

        if (ln < TT) al[ln] = startt[ln] + d_emis[((size_t)b * SS) * TT + ln];
        __syncwarp();
        for (int s = 1; s < SS; s++) {
            int m = mask[(size_t)b * SS + s];
            float nv = 0.f;
            if (ln < TT) {
                float v[TT];
                float mx = -1e30f;
#pragma unroll
                for (int i = 0; i < TT; i++) {
                    v[i] = al[i] + tr[i * TT + ln];
                    mx = fmaxf(mx, v[i]);
                }
                float sum = 0.f;
#pragma unroll
                for (int i = 0; i < TT; i++) sum += expf(v[i] - mx);
                nv = mx + logf(sum) + d_emis[((size_t)b * SS + s) * TT + ln];
            }
            __syncwarp();
            if (ln < TT && m > 0) al[ln] = nv;
            __syncwarp();
        }
        if (ln == 0) {
            float mx = -1e30f;
            for (int j = 0; j < TT; j++) mx = fmaxf(mx, al[j] + endt[j]);
            float sum = 0.f;
            for (int j = 0; j < TT; j++) sum += expf(al[j] + endt[j] - mx);
            d_nd[b] = num - (mx + logf(sum));
        }
    } else {
        // ---- Viterbi decode ----
        if (ln < TT) al[ln] = startt[ln] + d_emis[((size_t)b * SS) * TT + ln];
        __syncwarp();
        for (int s = 1; s < SS; s++) {
            int m = mask[(size_t)b * SS + s];
            float nv = 0.f;
            int arg = 0;
            if (ln < TT) {
                float mx = -1e30f;
#pragma unroll
                for (int i = 0; i < TT; i++) {
                    float v = al[i] + tr[i * TT + ln];
                    if (v > mx) { mx = v; arg = i; }
                }
                nv = mx + d_emis[((size_t)b * SS + s) * TT + ln];
            }
            __syncwarp();
            if (ln < TT) {
                if (m > 0) { al[ln] = nv; bp[s - 1][ln] = (unsigned char)arg; }
                else bp[s - 1][ln] = (unsigned char)ln;
            }
            __syncwarp();
        }
        if (ln == 0) {
            float mx = -1e30f;
            int lt = 0;
            for (int j = 0; j < TT; j++) {
                float v = al[j] + endt[j];
                if (v > mx) { mx = v; lt = j; }
            }
            tok_out[(size_t)b * SS + (SS - 1)] = (float)lt;
            int tg = lt;
            for (int s = SS - 2; s >= 0; s--) {
                tg = bp[s][tg];
                tok_out[(size_t)b * SS + s] = (float)tg;
            }
        }
    }
}

// ---------------- final loss reduce ----------------
__global__ void __launch_bounds__(64) k_final(float* __restrict__ out) {
    int tid = threadIdx.x;
    float v = d_nd[tid];
#pragma unroll
    for (int off = 16; off > 0; off >>= 1) v += __shfl_down_sync(0xffffffffu, v, off);
    __shared__ float w[2];
    if ((tid & 31) == 0) w[tid >> 5] = v;
    __syncthreads();
    if (tid == 0) out[0] = -(w[0] + w[1]) / (float)BB;
}

// ---------------- launch ----------------
extern "C" void kernel_launch(void* const* d_in, const int* in_sizes, int n_in,
                              void* d_out, int out_size) {
    const int* tok     = (const int*)d_in[0];
    const int* ctok    = (const int*)d_in[1];
    const int* labels  = (const int*)d_in[2];
    const int* amask   = (const int*)d_in[3];
    const float* wemb  = (const float*)d_in[4];
    const float* cemb  = (const float*)d_in[5];
    const float* convw = (const float*)d_in[6];
    const float* convb = (const float*)d_in[7];
    const float* wihf  = (const float*)d_in[8];
    const float* whhf  = (const float*)d_in[9];
    const float* bf    = (const float*)d_in[10];
    const float* wihb  = (const float*)d_in[11];
    const float* whhb  = (const float*)d_in[12];
    const float* bb    = (const float*)d_in[13];
    const float* clsw  = (const float*)d_in[14];
    const float* clsb  = (const float*)d_in[15];
    const float* startt = (const float*)d_in[16];
    const float* endt   = (const float*)d_in[17];
    const float* trans  = (const float*)d_in[18];
    float* out = (float*)d_out;
    int tok_off = out_size - BB * SS;
    if (tok_off < 0) tok_off = 0;

    k_init<<<1, 32>>>();
    k_embed<<<BS, 128>>>(tok, ctok, wemb, cemb, convw, convb);
    dim3 gg(BS / 128, G4 / 64, 2);
    k_gemm_gx<<<gg, 256>>>(wihf, bf, wihb, bb);
    k_lstm<<<256, 256>>>(whhf, whhb);
    k_emis<<<BS / 8, 256>>>(clsw, clsb);
    k_crf<<<2 * BB, 32>>>(labels, amask, startt, endt, trans, out + tok_off);
    k_final<<<1, 64>>>(out);
}

// round 14
// speedup vs baseline: 1.8427x; 1.0317x over previous
#include <cuda_runtime.h>
#include <math.h>
#include <stdint.h>

#define BB 64
#define SS 512
#define BS (BB*SS)
#define LL 16
#define WD 200
#define CD 30
#define FN 4
#define CF 120
#define KW 3
#define DD 320
#define HH 256
#define G4 1024
#define TT 17
#define LC 14

// ---------------- static scratch (no allocs allowed) ----------------
__device__ float d_z[BS * DD];                    // [B*S, 320]
__device__ float d_gx[2][(size_t)SS * BB * G4];   // [dir][S,B,1024]
__device__ float d_hs[2][(size_t)SS * BB * HH];   // [dir][S,B,256]
__device__ float d_h2[16][2][HH * 8];             // [grp][parity][k*8+b] h exchange
__device__ float d_emis[(size_t)BS * TT];         // [B,S,17]
__device__ float d_nd[BB];
__device__ int   d_ctr[16];

__device__ __forceinline__ float sigf(float x) { return 1.0f / (1.0f + expf(-x)); }

__device__ __forceinline__ int acq_load(const int* p) {
    int v;
    asm volatile("ld.global.acquire.gpu.b32 %0,[%1];" : "=r"(v) : "l"(p) : "memory");
    return v;
}
// fire-and-forget release increment (REDG, no return trip, no MEMBAR needed)
__device__ __forceinline__ void red_release_add(int* p, int v) {
    asm volatile("red.release.gpu.global.add.u32 [%0],%1;" :: "l"(p), "r"(v) : "memory");
}

// ---- packed f32x2 helpers (sm_103a FFMA2) ----
__device__ __forceinline__ unsigned long long fdup(float w) {
    unsigned long long d;
    asm("mov.b64 %0, {%1, %1};" : "=l"(d) : "f"(w));
    return d;
}
__device__ __forceinline__ void ffma2(unsigned long long& a, unsigned long long x,
                                      unsigned long long y) {
    asm("fma.rn.f32x2 %0, %1, %2, %0;" : "+l"(a) : "l"(x), "l"(y));
}
__device__ __forceinline__ unsigned long long addx2(unsigned long long a,
                                                    unsigned long long b) {
    unsigned long long r;
    asm("add.rn.f32x2 %0, %1, %2;" : "=l"(r) : "l"(a), "l"(b));
    return r;
}
__device__ __forceinline__ float2 unpk(unsigned long long a) {
    float2 f;
    asm("mov.b64 {%0, %1}, %2;" : "=f"(f.x), "=f"(f.y) : "l"(a));
    return f;
}

// ---------------- init (reset barrier counters each launch) ----------------
__global__ void k_init() {
    int t = threadIdx.x;
    if (t < 16) d_ctr[t] = 0;
}

// ---------------- embeddings + char CNN + concat ----------------
__global__ void __launch_bounds__(128) k_embed(const int* __restrict__ tok,
                                               const int* __restrict__ ctok,
                                               const float* __restrict__ wemb,
                                               const float* __restrict__ cemb,
                                               const float* __restrict__ convw,
                                               const float* __restrict__ convb) {
    int w = blockIdx.x;  // word = b*S + s
    __shared__ float ce[LL][CD];
    __shared__ int cid[LL];
    int tid = threadIdx.x;
    if (tid < LL) cid[tid] = ctok[(size_t)w * LL + tid];
    __syncthreads();
    for (int i = tid; i < LL * CD; i += 128) {
        int l = i / CD, c = i % CD;
        ce[l][c] = cemb[cid[l] * CD + c];
    }
    __syncthreads();
    if (tid < CF) {
        int o = tid, ic = o >> 2;
        float w0 = convw[o * 3 + 0], w1 = convw[o * 3 + 1], w2 = convw[o * 3 + 2];
        float m = -1e30f;
#pragma unroll
        for (int t = 0; t < LC; t++) {
            float v = ce[t][ic] * w0 + ce[t + 1][ic] * w1 + ce[t + 2][ic] * w2;
            m = fmaxf(m, v);
        }
        d_z[(size_t)w * DD + WD + o] = m + convb[o];
    }
    const float* wr = wemb + (size_t)tok[w] * WD;
    for (int j = tid; j < WD; j += 128) d_z[(size_t)w * DD + j] = wr[j];
}

// ---------------- input-side GEMM with FFMA2: z[BS,320] @ W^T -> gx ----------------
__global__ void __launch_bounds__(256, 2) k_gemm_gx(const float* __restrict__ Wf,
                                                    const float* __restrict__ biasf,
                                                    const float* __restrict__ Wb,
                                                    const float* __restrict__ biasb) {
    int dir = blockIdx.z;
    const float* __restrict__ Wm = dir ? Wb : Wf;
    const float* __restrict__ bias = dir ? biasb : biasf;
    float* out = d_gx[dir];
    const float* __restrict__ Z = d_z;

    int mBase = blockIdx.x * 128;
    int nBase = blockIdx.y * 64;

    __shared__ float As[16][132];
    __shared__ float Bs[16][68];

    int tid = threadIdx.x;
    int ty = tid >> 4;
    int tx = tid & 15;

    unsigned long long acc2[8][2];
#pragma unroll
    for (int i = 0; i < 8; i++) { acc2[i][0] = 0ull; acc2[i][1] = 0ull; }

    for (int k0 = 0; k0 < DD; k0 += 16) {
#pragma unroll
        for (int r = 0; r < 2; r++) {
            int idx = tid + r * 256;
            int row = idx >> 2, kq = idx & 3;
            float4 v = *(const float4*)&Z[(size_t)(mBase + row) * DD + k0 + kq * 4];
            As[kq * 4 + 0][row] = v.x;
            As[kq * 4 + 1][row] = v.y;
            As[kq * 4 + 2][row] = v.z;
            As[kq * 4 + 3][row] = v.w;
        }
        {
            int row = tid >> 2, kq = tid & 3;
            float4 v = *(const float4*)&Wm[(size_t)(nBase + row) * DD + k0 + kq * 4];
            Bs[kq * 4 + 0][row] = v.x;
            Bs[kq * 4 + 1][row] = v.y;
            Bs[kq * 4 + 2][row] = v.z;
            Bs[kq * 4 + 3][row] = v.w;
        }
        __syncthreads();
#pragma unroll
        for (int kk = 0; kk < 16; kk++) {
            float4 a0 = *(const float4*)&As[kk][ty * 8];
            float4 a1 = *(const float4*)&As[kk][ty * 8 + 4];
            ulonglong2 bq = *(const ulonglong2*)&Bs[kk][tx * 4];
            float av[8] = {a0.x, a0.y, a0.z, a0.w, a1.x, a1.y, a1.z, a1.w};
#pragma unroll
            for (int i = 0; i < 8; i++) {
                unsigned long long ad = fdup(av[i]);
                ffma2(acc2[i][0], bq.x, ad);
                ffma2(acc2[i][1], bq.y, ad);
            }
        }
        __syncthreads();
    }

    float bq0 = bias[nBase + tx * 4 + 0], bq1 = bias[nBase + tx * 4 + 1];
    float bq2 = bias[nBase + tx * 4 + 2], bq3 = bias[nBase + tx * 4 + 3];
#pragma unroll
    for (int i = 0; i < 8; i++) {
        int m = mBase + ty * 8 + i;
        int b = m >> 9, s = m & 511;
        size_t ro = ((size_t)s * BB + b) * (size_t)G4 + nBase + tx * 4;
        float2 p0 = unpk(acc2[i][0]);
        float2 p1 = unpk(acc2[i][1]);
        float4 o4;
        o4.x = p0.x + bq0;
        o4.y = p0.y + bq1;
        o4.z = p1.x + bq2;
        o4.w = p1.y + bq3;
        *(float4*)&out[ro] = o4;
    }
}

// ---------------- BiLSTM: 256 CTAs (16 groups x 16 slices), 256 thr, 2 CTAs/SM ----
// R13 structure (best verified). ONE change: publish = bar.sync + tid0
// red.release.gpu.add (REDG, fire-and-forget, release-ordered) — removes the
// 256-thread gpu-scope MEMBAR (which also drained the scattered d_hs history
// stores) and the atomic return trip from the per-step critical chain.
#define NSL 16
#define KSL 16
__global__ void __launch_bounds__(256, 2)
k_lstm(const float* __restrict__ whf, const float* __restrict__ whb) {
    __shared__ float h_sm[2 * HH * 8];   // [parity][256 k][8 batch]
    __shared__ float g_sm[64 * 8];       // [local gate row][8 batch]
    __shared__ float c_sm[KSL * 8];      // [k*8+b]

    int blk = blockIdx.x;
    int slice = blk & (NSL - 1);
    int grp = blk >> 4;          // 0..15
    int dir = grp >> 3;
    int bg = grp & 7;
    const float* Wd = dir ? whb : whf;
    int tid = threadIdx.x;
    int row = tid >> 2;          // 0..63 local gate row
    int sub = tid & 3;           // k-interleave lane
    int gt = row >> 4;           // gate 0..3
    int kl = row & 15;
    int ks = slice * KSL;
    int gr = gt * 256 + ks + kl; // gate row in [0,1024)
    const float* gxp = d_gx[dir];
    float* hsp = d_hs[dir];
    int b0 = bg * 8;

    // W into registers: w_reg[kk] = W[gr][4*kk + sub]
    float w_reg[64];
    {
        const float* wr = Wd + (size_t)gr * HH + sub;
#pragma unroll
        for (int kk = 0; kk < 64; kk++) w_reg[kk] = __ldg(wr + 4 * kk);
    }
    if (tid < KSL * 8) c_sm[tid] = 0.f;
    __syncthreads();

    // preload gx for step 0 (sub==0 threads hold gxn for their row)
    float gxn[8];
    if (sub == 0) {
        int t0 = dir ? (SS - 1) : 0;
        const float* gxr = gxp + ((size_t)t0 * BB + b0) * G4 + gr;
#pragma unroll
        for (int b = 0; b < 8; b++) gxn[b] = __ldg(gxr + (size_t)b * G4);
    }

    for (int s = 0; s < SS; s++) {
        int t = dir ? (SS - 1 - s) : s;
        unsigned long long a0 = 0ull, a1 = 0ull, a2 = 0ull, a3 = 0ull;

        if (s > 0) {
            int parp = (s & 1) ^ 1;   // parity of step s-1
            // wait for all 16 CTAs of the group to finish step s-1
            if (tid == 0) {
                int tgt = NSL * s;
                while (acq_load(&d_ctr[grp]) < tgt) {}
            }
            __syncthreads();
            // load h(s-1) from L2 into smem (512 float4 by 256 threads)
            {
                const float4* src = (const float4*)(d_h2[grp][parp]);
                float* dst = h_sm + parp * (HH * 8);
                float4 v0 = __ldcg(src + tid);
                float4 v1 = __ldcg(src + tid + 256);
                *(float4*)&dst[tid * 4] = v0;
                *(float4*)&dst[(tid + 256) * 4] = v1;
            }
            __syncthreads();

            const float* hb = h_sm + parp * (HH * 8) + sub * 8;
#pragma unroll
            for (int kk = 0; kk < 64; kk++) {
                unsigned long long wd = fdup(w_reg[kk]);
                const ulonglong2* hp = (const ulonglong2*)(hb + kk * 32);
                ulonglong2 q0 = hp[0];   // batches 0,1 | 2,3
                ulonglong2 q1 = hp[1];   // batches 4,5 | 6,7
                ffma2(a0, q0.x, wd);
                ffma2(a1, q0.y, wd);
                ffma2(a2, q1.x, wd);
                ffma2(a3, q1.y, wd);
            }
            // reduce across the 4 sub lanes (adjacent in warp)
            a0 = addx2(a0, __shfl_xor_sync(0xffffffffu, a0, 1));
            a1 = addx2(a1, __shfl_xor_sync(0xffffffffu, a1, 1));
            a2 = addx2(a2, __shfl_xor_sync(0xffffffffu, a2, 1));
            a3 = addx2(a3, __shfl_xor_sync(0xffffffffu, a3, 1));
            a0 = addx2(a0, __shfl_xor_sync(0xffffffffu, a0, 2));
            a1 = addx2(a1, __shfl_xor_sync(0xffffffffu, a1, 2));
            a2 = addx2(a2, __shfl_xor_sync(0xffffffffu, a2, 2));
            a3 = addx2(a3, __shfl_xor_sync(0xffffffffu, a3, 2));
        }
        if (sub == 0) {
            float2 p0 = unpk(a0), p1 = unpk(a1), p2 = unpk(a2), p3 = unpk(a3);
            float4 v0, v1;
            v0.x = p0.x + gxn[0]; v0.y = p0.y + gxn[1];
            v0.z = p1.x + gxn[2]; v0.w = p1.y + gxn[3];
            v1.x = p2.x + gxn[4]; v1.y = p2.y + gxn[5];
            v1.z = p3.x + gxn[6]; v1.w = p3.y + gxn[7];
            *(float4*)&g_sm[row * 8] = v0;
            *(float4*)&g_sm[row * 8 + 4] = v1;
        }
        __syncthreads();

        // elementwise LSTM cell: 128 tasks (k = tid>>3 in [0,16), b = tid&7)
        int par = s & 1;
        float hv = 0.f;
        if (tid < KSL * 8) {
            int k = tid >> 3;
            int b = tid & 7;
            float gi = g_sm[(0 * KSL + k) * 8 + b];
            float gf = g_sm[(1 * KSL + k) * 8 + b];
            float gg = g_sm[(2 * KSL + k) * 8 + b];
            float go = g_sm[(3 * KSL + k) * 8 + b];
            float c = c_sm[tid];
            float cn = sigf(gf) * c + sigf(gi) * tanhf(gg);
            hv = sigf(go) * tanhf(cn);
            c_sm[tid] = cn;
            __stcg(&d_h2[grp][par][(ks + k) * 8 + b], hv);
        }
        // prefetch next step's gx (independent of the barrier)
        if (sub == 0 && s + 1 < SS) {
            int tn = dir ? (SS - 2 - s) : (s + 1);
            const float* gxr = gxp + ((size_t)tn * BB + b0) * G4 + gr;
#pragma unroll
            for (int b = 0; b < 8; b++) gxn[b] = __ldg(gxr + (size_t)b * G4);
        }
        __syncthreads();   // h2 stores issued by all cell threads before publish
        if (tid == 0) red_release_add(&d_ctr[grp], 1);
        // history write AFTER publish — background stream, never fenced
        if (tid < KSL * 8) {
            int k = tid >> 3;
            int b = tid & 7;
            hsp[((size_t)t * BB + b0 + b) * HH + ks + k] = hv;
        }
    }
}

// ---------------- emissions: concat(hs_f, hs_b) @ cls_w^T + cls_b ----------------
__global__ void __launch_bounds__(256) k_emis(const float* __restrict__ clsw,
                                              const float* __restrict__ clsb) {
    __shared__ float cw[TT * 512];
    __shared__ float cb[32];
    int tid = threadIdx.x;
    for (int i = tid; i < TT * 512; i += 256) cw[i] = clsw[i];
    if (tid < TT) cb[tid] = clsb[tid];
    __syncthreads();

    int warp = tid >> 5, lane = tid & 31;
    int w = blockIdx.x * 8 + warp;
    int b = w >> 9, s = w & 511;
    const float* hf = d_hs[0] + ((size_t)s * BB + b) * HH;
    const float* hb = d_hs[1] + ((size_t)s * BB + b) * HH;
    float hv[16];
#pragma unroll
    for (int i = 0; i < 8; i++) {
        hv[i] = hf[lane + 32 * i];
        hv[8 + i] = hb[lane + 32 * i];
    }
#pragma unroll 1
    for (int o = 0; o < TT; o++) {
        const float* c0 = cw + o * 512;
        float sum = 0.f;
#pragma unroll
        for (int i = 0; i < 8; i++) {
            sum = fmaf(hv[i], c0[lane + 32 * i], sum);
            sum = fmaf(hv[8 + i], c0[256 + lane + 32 * i], sum);
        }
#pragma unroll
        for (int off = 16; off > 0; off >>= 1)
            sum += __shfl_down_sync(0xffffffffu, sum, off);
        if (lane == 0) d_emis[(size_t)w * TT + o] = sum + cb[o];
    }
}

// ---------------- CRF: blocks 0..63 = loss forward, 64..127 = Viterbi decode -------
__global__ void __launch_bounds__(32) k_crf(const int* __restrict__ labels,
                                            const int* __restrict__ mask,
                                            const float* __restrict__ startt,
                                            const float* __restrict__ endt,
                                            const float* __restrict__ trans,
                                            float* __restrict__ tok_out) {
    int which = blockIdx.x >> 6;
    int b = blockIdx.x & 63;
    int ln = threadIdx.x;
    __shared__ float tr[TT * TT];
    __shared__ float al[TT];
    __shared__ unsigned char bp[SS - 1][TT];
    for (int i = ln; i < TT * TT; i += 32) tr[i] = trans[i];
    __syncwarp();

    if (which == 0) {
        // ---- loss ----
        float part = 0.f;
        for (int s = ln; s < SS; s += 32) {
            int tg = labels[(size_t)b * SS + s];
            float mf = (float)mask[(size_t)b * SS + s];
            part += d_emis[((size_t)b * SS + s) * TT + tg] * mf;
            if (s >= 1) {
                int tp = labels[(size_t)b * SS + s - 1];
                part += tr[tp * TT + tg] * mf;
            }
        }
#pragma unroll
        for (int off = 16; off > 0; off >>= 1)
            part += __shfl_down_sync(0xffffffffu, part, off);
        float num = 0.f;
        if (ln == 0) {
            num = part + startt[labels[(size_t)b * SS]];
            int cnt = 0;
            for (int s = 0; s < SS; s++) cnt += mask[(size_t)b * SS + s];
            num += endt[labels[(size_t)b * SS + cnt - 1]];
        }

        if (ln < TT) al[ln] = startt[ln] + d_emis[((size_t)b * SS) * TT + ln];
        __syncwarp();
        for (int s = 1; s < SS; s++) {
            int m = mask[(size_t)b * SS + s];
            float nv = 0.f;
            if (ln < TT) {
                float v[TT];
                float mx = -1e30f;
#pragma unroll
                for (int i = 0; i < TT; i++) {
                    v[i] = al[i] + tr[i * TT + ln];
                    mx = fmaxf(mx, v[i]);
                }
                float sum = 0.f;
#pragma unroll
                for (int i = 0; i < TT; i++) sum += expf(v[i] - mx);
                nv = mx + logf(sum) + d_emis[((size_t)b * SS + s) * TT + ln];
            }
            __syncwarp();
            if (ln < TT && m > 0) al[ln] = nv;
            __syncwarp();
        }
        if (ln == 0) {
            float mx = -1e30f;
            for (int j = 0; j < TT; j++) mx = fmaxf(mx, al[j] + endt[j]);
            float sum = 0.f;
            for (int j = 0; j < TT; j++) sum += expf(al[j] + endt[j] - mx);
            d_nd[b] = num - (mx + logf(sum));
        }
    } else {
        // ---- Viterbi decode ----
        if (ln < TT) al[ln] = startt[ln] + d_emis[((size_t)b * SS) * TT + ln];
        __syncwarp();
        for (int s = 1; s < SS; s++) {
            int m = mask[(size_t)b * SS + s];
            float nv = 0.f;
            int arg = 0;
            if (ln < TT) {
                float mx = -1e30f;
#pragma unroll
                for (int i = 0; i < TT; i++) {
                    float v = al[i] + tr[i * TT + ln];
                    if (v > mx) { mx = v; arg = i; }
                }
                nv = mx + d_emis[((size_t)b * SS + s) * TT + ln];
            }
            __syncwarp();
            if (ln < TT) {
                if (m > 0) { al[ln] = nv; bp[s - 1][ln] = (unsigned char)arg; }
                else bp[s - 1][ln] = (unsigned char)ln;
            }
            __syncwarp();
        }
        if (ln == 0) {
            float mx = -1e30f;
            int lt = 0;
            for (int j = 0; j < TT; j++) {
                float v = al[j] + endt[j];
                if (v > mx) { mx = v; lt = j; }
            }
            tok_out[(size_t)b * SS + (SS - 1)] = (float)lt;
            int tg = lt;
            for (int s = SS - 2; s >= 0; s--) {
                tg = bp[s][tg];
                tok_out[(size_t)b * SS + s] = (float)tg;
            }
        }
    }
}

// ---------------- final loss reduce ----------------
__global__ void __launch_bounds__(64) k_final(float* __restrict__ out) {
    int tid = threadIdx.x;
    float v = d_nd[tid];
#pragma unroll
    for (int off = 16; off > 0; off >>= 1) v += __shfl_down_sync(0xffffffffu, v, off);
    __shared__ float w[2];
    if ((tid & 31) == 0) w[tid >> 5] = v;
    __syncthreads();
    if (tid == 0) out[0] = -(w[0] + w[1]) / (float)BB;
}

// ---------------- launch ----------------
extern "C" void kernel_launch(void* const* d_in, const int* in_sizes, int n_in,
                              void* d_out, int out_size) {
    const int* tok     = (const int*)d_in[0];
    const int* ctok    = (const int*)d_in[1];
    const int* labels  = (const int*)d_in[2];
    const int* amask   = (const int*)d_in[3];
    const float* wemb  = (const float*)d_in[4];
    const float* cemb  = (const float*)d_in[5];
    const float* convw = (const float*)d_in[6];
    const float* convb = (const float*)d_in[7];
    const float* wihf  = (const float*)d_in[8];
    const float* whhf  = (const float*)d_in[9];
    const float* bf    = (const float*)d_in[10];
    const float* wihb  = (const float*)d_in[11];
    const float* whhb  = (const float*)d_in[12];
    const float* bb    = (const float*)d_in[13];
    const float* clsw  = (const float*)d_in[14];
    const float* clsb  = (const float*)d_in[15];
    const float* startt = (const float*)d_in[16];
    const float* endt   = (const float*)d_in[17];
    const float* trans  = (const float*)d_in[18];
    float* out = (float*)d_out;
    int tok_off = out_size - BB * SS;
    if (tok_off < 0) tok_off = 0;

    k_init<<<1, 32>>>();
    k_embed<<<BS, 128>>>(tok, ctok, wemb, cemb, convw, convb);
    dim3 gg(BS / 128, G4 / 64, 2);
    k_gemm_gx<<<gg, 256>>>(wihf, bf, wihb, bb);
    k_lstm<<<256, 256>>>(whhf, whhb);
    k_emis<<<BS / 8, 256>>>(clsw, clsb);
    k_crf<<<2 * BB, 32>>>(labels, amask, startt, endt, trans, out + tok_off);
    k_final<<<1, 64>>>(out);
}

// round 15
// speedup vs baseline: 1.8717x; 1.0158x over previous
#include <cuda_runtime.h>
#include <math.h>
#include <stdint.h>

#define BB 64
#define SS 512
#define BS (BB*SS)
#define LL 16
#define WD 200
#define CD 30
#define FN 4
#define CF 120
#define KW 3
#define DD 320
#define HH 256
#define G4 1024
#define TT 17
#define LC 14

// ---------------- static scratch (no allocs allowed) ----------------
__device__ float d_z[BS * DD];                    // [B*S, 320]
__device__ float d_gx[2][(size_t)SS * BB * G4];   // [dir][S,B,1024]
__device__ float d_hs[2][(size_t)SS * BB * HH];   // [dir][S,B,256]
__device__ float d_h2[16][2][HH * 8];             // [grp][parity][k*8+b] h exchange
__device__ float d_emis[(size_t)BS * TT];         // [B,S,17]
__device__ float d_nd[BB];
__device__ int   d_ctr[16];

__device__ __forceinline__ float sigf(float x) { return 1.0f / (1.0f + expf(-x)); }

__device__ __forceinline__ int acq_load(const int* p) {
    int v;
    asm volatile("ld.global.acquire.gpu.b32 %0,[%1];" : "=r"(v) : "l"(p) : "memory");
    return v;
}
// fire-and-forget release increment (REDG, no return trip, no MEMBAR needed)
__device__ __forceinline__ void red_release_add(int* p, int v) {
    asm volatile("red.release.gpu.global.add.u32 [%0],%1;" :: "l"(p), "r"(v) : "memory");
}

// ---- packed f32x2 helpers (sm_103a FFMA2) ----
__device__ __forceinline__ unsigned long long fdup(float w) {
    unsigned long long d;
    asm("mov.b64 %0, {%1, %1};" : "=l"(d) : "f"(w));
    return d;
}
__device__ __forceinline__ void ffma2(unsigned long long& a, unsigned long long x,
                                      unsigned long long y) {
    asm("fma.rn.f32x2 %0, %1, %2, %0;" : "+l"(a) : "l"(x), "l"(y));
}
__device__ __forceinline__ unsigned long long addx2(unsigned long long a,
                                                    unsigned long long b) {
    unsigned long long r;
    asm("add.rn.f32x2 %0, %1, %2;" : "=l"(r) : "l"(a), "l"(b));
    return r;
}
__device__ __forceinline__ float2 unpk(unsigned long long a) {
    float2 f;
    asm("mov.b64 {%0, %1}, %2;" : "=f"(f.x), "=f"(f.y) : "l"(a));
    return f;
}

// ---------------- embeddings + char CNN + concat (+ ctr reset in block 0) ---------
__global__ void __launch_bounds__(128) k_embed(const int* __restrict__ tok,
                                               const int* __restrict__ ctok,
                                               const float* __restrict__ wemb,
                                               const float* __restrict__ cemb,
                                               const float* __restrict__ convw,
                                               const float* __restrict__ convb) {
    int w = blockIdx.x;  // word = b*S + s
    __shared__ float ce[LL][CD];
    __shared__ int cid[LL];
    int tid = threadIdx.x;
    if (w == 0 && tid < 16) d_ctr[tid] = 0;   // barrier counters reset (pre-lstm)
    if (tid < LL) cid[tid] = ctok[(size_t)w * LL + tid];
    __syncthreads();
    for (int i = tid; i < LL * CD; i += 128) {
        int l = i / CD, c = i % CD;
        ce[l][c] = cemb[cid[l] * CD + c];
    }
    __syncthreads();
    if (tid < CF) {
        int o = tid, ic = o >> 2;
        float w0 = convw[o * 3 + 0], w1 = convw[o * 3 + 1], w2 = convw[o * 3 + 2];
        float m = -1e30f;
#pragma unroll
        for (int t = 0; t < LC; t++) {
            float v = ce[t][ic] * w0 + ce[t + 1][ic] * w1 + ce[t + 2][ic] * w2;
            m = fmaxf(m, v);
        }
        d_z[(size_t)w * DD + WD + o] = m + convb[o];
    }
    const float* wr = wemb + (size_t)tok[w] * WD;
    for (int j = tid; j < WD; j += 128) d_z[(size_t)w * DD + j] = wr[j];
}

// ---------------- input-side GEMM, double-buffered smem, FFMA2 --------------------
// Same math/accumulation order as before; LDG for tile i+1 overlaps compute of
// tile i; one __syncthreads per k-tile.
__global__ void __launch_bounds__(256, 2) k_gemm_gx(const float* __restrict__ Wf,
                                                    const float* __restrict__ biasf,
                                                    const float* __restrict__ Wb,
                                                    const float* __restrict__ biasb) {
    int dir = blockIdx.z;
    const float* __restrict__ Wm = dir ? Wb : Wf;
    const float* __restrict__ bias = dir ? biasb : biasf;
    float* out = d_gx[dir];
    const float* __restrict__ Z = d_z;

    int mBase = blockIdx.x * 128;
    int nBase = blockIdx.y * 64;

    __shared__ float As[2][16][132];
    __shared__ float Bs[2][16][68];

    int tid = threadIdx.x;
    int ty = tid >> 4;
    int tx = tid & 15;
    int ar = tid >> 2;       // 0..63
    int kq = tid & 3;        // 0..3

    const float* zp0 = Z + (size_t)(mBase + ar) * DD + kq * 4;
    const float* zp1 = Z + (size_t)(mBase + 64 + ar) * DD + kq * 4;
    const float* wp  = Wm + (size_t)(nBase + ar) * DD + kq * 4;

    unsigned long long acc2[8][2];
#pragma unroll
    for (int i = 0; i < 8; i++) { acc2[i][0] = 0ull; acc2[i][1] = 0ull; }

    float4 ra0, ra1, rb;
    // prologue: load tile 0
    ra0 = *(const float4*)(zp0);
    ra1 = *(const float4*)(zp1);
    rb  = *(const float4*)(wp);
    {
        As[0][kq * 4 + 0][ar] = ra0.x; As[0][kq * 4 + 1][ar] = ra0.y;
        As[0][kq * 4 + 2][ar] = ra0.z; As[0][kq * 4 + 3][ar] = ra0.w;
        As[0][kq * 4 + 0][64 + ar] = ra1.x; As[0][kq * 4 + 1][64 + ar] = ra1.y;
        As[0][kq * 4 + 2][64 + ar] = ra1.z; As[0][kq * 4 + 3][64 + ar] = ra1.w;
        Bs[0][kq * 4 + 0][ar] = rb.x; Bs[0][kq * 4 + 1][ar] = rb.y;
        Bs[0][kq * 4 + 2][ar] = rb.z; Bs[0][kq * 4 + 3][ar] = rb.w;
    }
    __syncthreads();

#pragma unroll 1
    for (int it = 0; it < DD / 16; it++) {
        int p = it & 1;
        if (it + 1 < DD / 16) {
            int k0 = 16 * (it + 1);
            ra0 = *(const float4*)(zp0 + k0);
            ra1 = *(const float4*)(zp1 + k0);
            rb  = *(const float4*)(wp + k0);
        }
#pragma unroll
        for (int kk = 0; kk < 16; kk++) {
            float4 a0 = *(const float4*)&As[p][kk][ty * 8];
            float4 a1 = *(const float4*)&As[p][kk][ty * 8 + 4];
            ulonglong2 bq = *(const ulonglong2*)&Bs[p][kk][tx * 4];
            float av[8] = {a0.x, a0.y, a0.z, a0.w, a1.x, a1.y, a1.z, a1.w};
#pragma unroll
            for (int i = 0; i < 8; i++) {
                unsigned long long ad = fdup(av[i]);
                ffma2(acc2[i][0], bq.x, ad);
                ffma2(acc2[i][1], bq.y, ad);
            }
        }
        if (it + 1 < DD / 16) {
            int q = p ^ 1;
            As[q][kq * 4 + 0][ar] = ra0.x; As[q][kq * 4 + 1][ar] = ra0.y;
            As[q][kq * 4 + 2][ar] = ra0.z; As[q][kq * 4 + 3][ar] = ra0.w;
            As[q][kq * 4 + 0][64 + ar] = ra1.x; As[q][kq * 4 + 1][64 + ar] = ra1.y;
            As[q][kq * 4 + 2][64 + ar] = ra1.z; As[q][kq * 4 + 3][64 + ar] = ra1.w;
            Bs[q][kq * 4 + 0][ar] = rb.x; Bs[q][kq * 4 + 1][ar] = rb.y;
            Bs[q][kq * 4 + 2][ar] = rb.z; Bs[q][kq * 4 + 3][ar] = rb.w;
        }
        __syncthreads();
    }

    float bq0 = bias[nBase + tx * 4 + 0], bq1 = bias[nBase + tx * 4 + 1];
    float bq2 = bias[nBase + tx * 4 + 2], bq3 = bias[nBase + tx * 4 + 3];
#pragma unroll
    for (int i = 0; i < 8; i++) {
        int m = mBase + ty * 8 + i;
        int b = m >> 9, s = m & 511;
        size_t ro = ((size_t)s * BB + b) * (size_t)G4 + nBase + tx * 4;
        float2 p0 = unpk(acc2[i][0]);
        float2 p1 = unpk(acc2[i][1]);
        float4 o4;
        o4.x = p0.x + bq0;
        o4.y = p0.y + bq1;
        o4.z = p1.x + bq2;
        o4.w = p1.y + bq3;
        *(float4*)&out[ro] = o4;
    }
}

// ---------------- BiLSTM: R14 (best verified) — unchanged -------------------------
#define NSL 16
#define KSL 16
__global__ void __launch_bounds__(256, 2)
k_lstm(const float* __restrict__ whf, const float* __restrict__ whb) {
    __shared__ float h_sm[2 * HH * 8];   // [parity][256 k][8 batch]
    __shared__ float g_sm[64 * 8];       // [local gate row][8 batch]
    __shared__ float c_sm[KSL * 8];      // [k*8+b]

    int blk = blockIdx.x;
    int slice = blk & (NSL - 1);
    int grp = blk >> 4;          // 0..15
    int dir = grp >> 3;
    int bg = grp & 7;
    const float* Wd = dir ? whb : whf;
    int tid = threadIdx.x;
    int row = tid >> 2;          // 0..63 local gate row
    int sub = tid & 3;           // k-interleave lane
    int gt = row >> 4;           // gate 0..3
    int kl = row & 15;
    int ks = slice * KSL;
    int gr = gt * 256 + ks + kl; // gate row in [0,1024)
    const float* gxp = d_gx[dir];
    float* hsp = d_hs[dir];
    int b0 = bg * 8;

    // W into registers: w_reg[kk] = W[gr][4*kk + sub]
    float w_reg[64];
    {
        const float* wr = Wd + (size_t)gr * HH + sub;
#pragma unroll
        for (int kk = 0; kk < 64; kk++) w_reg[kk] = __ldg(wr + 4 * kk);
    }
    if (tid < KSL * 8) c_sm[tid] = 0.f;
    __syncthreads();

    // preload gx for step 0 (sub==0 threads hold gxn for their row)
    float gxn[8];
    if (sub == 0) {
        int t0 = dir ? (SS - 1) : 0;
        const float* gxr = gxp + ((size_t)t0 * BB + b0) * G4 + gr;
#pragma unroll
        for (int b = 0; b < 8; b++) gxn[b] = __ldg(gxr + (size_t)b * G4);
    }

    for (int s = 0; s < SS; s++) {
        int t = dir ? (SS - 1 - s) : s;
        unsigned long long a0 = 0ull, a1 = 0ull, a2 = 0ull, a3 = 0ull;

        if (s > 0) {
            int parp = (s & 1) ^ 1;   // parity of step s-1
            // wait for all 16 CTAs of the group to finish step s-1
            if (tid == 0) {
                int tgt = NSL * s;
                while (acq_load(&d_ctr[grp]) < tgt) {}
            }
            __syncthreads();
            // load h(s-1) from L2 into smem (512 float4 by 256 threads)
            {
                const float4* src = (const float4*)(d_h2[grp][parp]);
                float* dst = h_sm + parp * (HH * 8);
                float4 v0 = __ldcg(src + tid);
                float4 v1 = __ldcg(src + tid + 256);
                *(float4*)&dst[tid * 4] = v0;
                *(float4*)&dst[(tid + 256) * 4] = v1;
            }
            __syncthreads();

            const float* hb = h_sm + parp * (HH * 8) + sub * 8;
#pragma unroll
            for (int kk = 0; kk < 64; kk++) {
                unsigned long long wd = fdup(w_reg[kk]);
                const ulonglong2* hp = (const ulonglong2*)(hb + kk * 32);
                ulonglong2 q0 = hp[0];   // batches 0,1 | 2,3
                ulonglong2 q1 = hp[1];   // batches 4,5 | 6,7
                ffma2(a0, q0.x, wd);
                ffma2(a1, q0.y, wd);
                ffma2(a2, q1.x, wd);
                ffma2(a3, q1.y, wd);
            }
            // reduce across the 4 sub lanes (adjacent in warp)
            a0 = addx2(a0, __shfl_xor_sync(0xffffffffu, a0, 1));
            a1 = addx2(a1, __shfl_xor_sync(0xffffffffu, a1, 1));
            a2 = addx2(a2, __shfl_xor_sync(0xffffffffu, a2, 1));
            a3 = addx2(a3, __shfl_xor_sync(0xffffffffu, a3, 1));
            a0 = addx2(a0, __shfl_xor_sync(0xffffffffu, a0, 2));
            a1 = addx2(a1, __shfl_xor_sync(0xffffffffu, a1, 2));
            a2 = addx2(a2, __shfl_xor_sync(0xffffffffu, a2, 2));
            a3 = addx2(a3, __shfl_xor_sync(0xffffffffu, a3, 2));
        }
        if (sub == 0) {
            float2 p0 = unpk(a0), p1 = unpk(a1), p2 = unpk(a2), p3 = unpk(a3);
            float4 v0, v1;
            v0.x = p0.x + gxn[0]; v0.y = p0.y + gxn[1];
            v0.z = p1.x + gxn[2]; v0.w = p1.y + gxn[3];
            v1.x = p2.x + gxn[4]; v1.y = p2.y + gxn[5];
            v1.z = p3.x + gxn[6]; v1.w = p3.y + gxn[7];
            *(float4*)&g_sm[row * 8] = v0;
            *(float4*)&g_sm[row * 8 + 4] = v1;
        }
        __syncthreads();

        // elementwise LSTM cell: 128 tasks (k = tid>>3 in [0,16), b = tid&7)
        int par = s & 1;
        float hv = 0.f;
        if (tid < KSL * 8) {
            int k = tid >> 3;
            int b = tid & 7;
            float gi = g_sm[(0 * KSL + k) * 8 + b];
            float gf = g_sm[(1 * KSL + k) * 8 + b];
            float gg = g_sm[(2 * KSL + k) * 8 + b];
            float go = g_sm[(3 * KSL + k) * 8 + b];
            float c = c_sm[tid];
            float cn = sigf(gf) * c + sigf(gi) * tanhf(gg);
            hv = sigf(go) * tanhf(cn);
            c_sm[tid] = cn;
            __stcg(&d_h2[grp][par][(ks + k) * 8 + b], hv);
        }
        // prefetch next step's gx (independent of the barrier)
        if (sub == 0 && s + 1 < SS) {
            int tn = dir ? (SS - 2 - s) : (s + 1);
            const float* gxr = gxp + ((size_t)tn * BB + b0) * G4 + gr;
#pragma unroll
            for (int b = 0; b < 8; b++) gxn[b] = __ldg(gxr + (size_t)b * G4);
        }
        __syncthreads();   // h2 stores issued by all cell threads before publish
        if (tid == 0) red_release_add(&d_ctr[grp], 1);
        // history write AFTER publish — background stream, never fenced
        if (tid < KSL * 8) {
            int k = tid >> 3;
            int b = tid & 7;
            hsp[((size_t)t * BB + b0 + b) * HH + ks + k] = hv;
        }
    }
}

// ---------------- emissions: concat(hs_f, hs_b) @ cls_w^T + cls_b ----------------
__global__ void __launch_bounds__(256) k_emis(const float* __restrict__ clsw,
                                              const float* __restrict__ clsb) {
    __shared__ float cw[TT * 512];
    __shared__ float cb[32];
    int tid = threadIdx.x;
    for (int i = tid; i < TT * 512; i += 256) cw[i] = clsw[i];
    if (tid < TT) cb[tid] = clsb[tid];
    __syncthreads();

    int warp = tid >> 5, lane = tid & 31;
    int w = blockIdx.x * 8 + warp;
    int b = w >> 9, s = w & 511;
    const float* hf = d_hs[0] + ((size_t)s * BB + b) * HH;
    const float* hb = d_hs[1] + ((size_t)s * BB + b) * HH;
    float hv[16];
#pragma unroll
    for (int i = 0; i < 8; i++) {
        hv[i] = hf[lane + 32 * i];
        hv[8 + i] = hb[lane + 32 * i];
    }
#pragma unroll 1
    for (int o = 0; o < TT; o++) {
        const float* c0 = cw + o * 512;
        float sum = 0.f;
#pragma unroll
        for (int i = 0; i < 8; i++) {
            sum = fmaf(hv[i], c0[lane + 32 * i], sum);
            sum = fmaf(hv[8 + i], c0[256 + lane + 32 * i], sum);
        }
#pragma unroll
        for (int off = 16; off > 0; off >>= 1)
            sum += __shfl_down_sync(0xffffffffu, sum, off);
        if (lane == 0) d_emis[(size_t)w * TT + o] = sum + cb[o];
    }
}

// ---------------- CRF: blocks 0..63 = loss forward, 64..127 = Viterbi decode -------
__global__ void __launch_bounds__(32) k_crf(const int* __restrict__ labels,
                                            const int* __restrict__ mask,
                                            const float* __restrict__ startt,
                                            const float* __restrict__ endt,
                                            const float* __restrict__ trans,
                                            float* __restrict__ tok_out) {
    int which = blockIdx.x >> 6;
    int b = blockIdx.x & 63;
    int ln = threadIdx.x;
    __shared__ float tr[TT * TT];
    __shared__ float al[TT];
    __shared__ unsigned char bp[SS - 1][TT];
    for (int i = ln; i < TT * TT; i += 32) tr[i] = trans[i];
    __syncwarp();

    if (which == 0) {
        // ---- loss ----
        float part = 0.f;
        for (int s = ln; s < SS; s += 32) {
            int tg = labels[(size_t)b * SS + s];
            float mf = (float)mask[(size_t)b * SS + s];
            part += d_emis[((size_t)b * SS + s) * TT + tg] * mf;
            if (s >= 1) {
                int tp = labels[(size_t)b * SS + s - 1];
                part += tr[tp * TT + tg] * mf;
            }
        }
#pragma unroll
        for (int off = 16; off > 0; off >>= 1)
            part += __shfl_down_sync(0xffffffffu, part, off);
        float num = 0.f;
        if (ln == 0) {
            num = part + startt[labels[(size_t)b * SS]];
            int cnt = 0;
            for (int s = 0; s < SS; s++) cnt += mask[(size_t)b * SS + s];
            num += endt[labels[(size_t)b * SS + cnt - 1]];
        }

        if (ln < TT) al[ln] = startt[ln] + d_emis[((size_t)b * SS) * TT + ln];
        __syncwarp();
        for (int s = 1; s < SS; s++) {
            int m = mask[(size_t)b * SS + s];
            float nv = 0.f;
            if (ln < TT) {
                float v[TT];
                float mx = -1e30f;
#pragma unroll
                for (int i = 0; i < TT; i++) {
                    v[i] = al[i] + tr[i * TT + ln];
                    mx = fmaxf(mx, v[i]);
                }
                float sum = 0.f;
#pragma unroll
                for (int i = 0; i < TT; i++) sum += expf(v[i] - mx);
                nv = mx + logf(sum) + d_emis[((size_t)b * SS + s) * TT + ln];
            }
            __syncwarp();
            if (ln < TT && m > 0) al[ln] = nv;
            __syncwarp();
        }
        if (ln == 0) {
            float mx = -1e30f;
            for (int j = 0; j < TT; j++) mx = fmaxf(mx, al[j] + endt[j]);
            float sum = 0.f;
            for (int j = 0; j < TT; j++) sum += expf(al[j] + endt[j] - mx);
            d_nd[b] = num - (mx + logf(sum));
        }
    } else {
        // ---- Viterbi decode ----
        if (ln < TT) al[ln] = startt[ln] + d_emis[((size_t)b * SS) * TT + ln];
        __syncwarp();
        for (int s = 1; s < SS; s++) {
            int m = mask[(size_t)b * SS + s];
            float nv = 0.f;
            int arg = 0;
            if (ln < TT) {
                float mx = -1e30f;
#pragma unroll
                for (int i = 0; i < TT; i++) {
                    float v = al[i] + tr[i * TT + ln];
                    if (v > mx) { mx = v; arg = i; }
                }
                nv = mx + d_emis[((size_t)b * SS + s) * TT + ln];
            }
            __syncwarp();
            if (ln < TT) {
                if (m > 0) { al[ln] = nv; bp[s - 1][ln] = (unsigned char)arg; }
                else bp[s - 1][ln] = (unsigned char)ln;
            }
            __syncwarp();
        }
        if (ln == 0) {
            float mx = -1e30f;
            int lt = 0;
            for (int j = 0; j < TT; j++) {
                float v = al[j] + endt[j];
                if (v > mx) { mx = v; lt = j; }
            }
            tok_out[(size_t)b * SS + (SS - 1)] = (float)lt;
            int tg = lt;
            for (int s = SS - 2; s >= 0; s--) {
                tg = bp[s][tg];
                tok_out[(size_t)b * SS + s] = (float)tg;
            }
        }
    }
}

// ---------------- final loss reduce ----------------
__global__ void __launch_bounds__(64) k_final(float* __restrict__ out) {
    int tid = threadIdx.x;
    float v = d_nd[tid];
#pragma unroll
    for (int off = 16; off > 0; off >>= 1) v += __shfl_down_sync(0xffffffffu, v, off);
    __shared__ float w[2];
    if ((tid & 31) == 0) w[tid >> 5] = v;
    __syncthreads();
    if (tid == 0) out[0] = -(w[0] + w[1]) / (float)BB;
}

// ---------------- launch ----------------
extern "C" void kernel_launch(void* const* d_in, const int* in_sizes, int n_in,
                              void* d_out, int out_size) {
    const int* tok     = (const int*)d_in[0];
    const int* ctok    = (const int*)d_in[1];
    const int* labels  = (const int*)d_in[2];
    const int* amask   = (const int*)d_in[3];
    const float* wemb  = (const float*)d_in[4];
    const float* cemb  = (const float*)d_in[5];
    const float* convw = (const float*)d_in[6];
    const float* convb = (const float*)d_in[7];
    const float* wihf  = (const float*)d_in[8];
    const float* whhf  = (const float*)d_in[9];
    const float* bf    = (const float*)d_in[10];
    const float* wihb  = (const float*)d_in[11];
    const float* whhb  = (const float*)d_in[12];
    const float* bb    = (const float*)d_in[13];
    const float* clsw  = (const float*)d_in[14];
    const float* clsb  = (const float*)d_in[15];
    const float* startt = (const float*)d_in[16];
    const float* endt   = (const float*)d_in[17];
    const float* trans  = (const float*)d_in[18];
    float* out = (float*)d_out;
    int tok_off = out_size - BB * SS;
    if (tok_off < 0) tok_off = 0;

    k_embed<<<BS, 128>>>(tok, ctok, wemb, cemb, convw, convb);
    dim3 gg(BS / 128, G4 / 64, 2);
    k_gemm_gx<<<gg, 256>>>(wihf, bf, wihb, bb);
    k_lstm<<<256, 256>>>(whhf, whhb);
    k_emis<<<BS / 8, 256>>>(clsw, clsb);
    k_crf<<<2 * BB, 32>>>(labels, amask, startt, endt, trans, out + tok_off);
    k_final<<<1, 64>>>(out);
}